// round 13
// baseline (speedup 1.0000x reference)
#include <cuda_runtime.h>
#include <cuda_fp16.h>
#include <cstdint>
#include <math.h>

#define N_NODES 100000
#define N_EDGES 3200000
#define EPS_BN 1e-5f
#define EPS_NORM 1e-12f

// ---------------- device scratch (no allocation allowed) ----------------
__device__ __align__(16) float g_x0[N_NODES * 8];     // BN output (padded stride 8)
__device__ __align__(16) float g_x1[N_NODES * 64];    // conv1 output
__device__ __align__(16) float g_x2[N_NODES * 64];    // conv2 output
__device__ __align__(16) __half g_yh[N_NODES * 64];   // fp16 projected features (stride 64 or 8)
__device__ __align__(16) __half g_aggh[N_NODES * 64]; // conv2 accumulator (fp16 atomics)
__device__ __align__(32) float g_agg8[N_NODES * 8];   // conv1/conv3 accumulator (5 feats + cnt)
__device__ float g_cinv[N_NODES];                     // 1/max(cnt,1)
__device__ __align__(16) float g_part[148 * 16];      // BN per-block partials

// ---------------- vector reductions ----------------
__device__ __forceinline__ void red_add_v4(float* p, float4 v) {
    asm volatile("red.global.add.v4.f32 [%0], {%1,%2,%3,%4};"
                 :: "l"(p), "f"(v.x), "f"(v.y), "f"(v.z), "f"(v.w) : "memory");
}
__device__ __forceinline__ void red_add_v2(float* p, float a, float b) {
    asm volatile("red.global.add.v2.f32 [%0], {%1,%2};"
                 :: "l"(p), "f"(a), "f"(b) : "memory");
}
__device__ __forceinline__ void red_add_f32(float* p, float a) {
    asm volatile("red.global.add.f32 [%0], %1;"
                 :: "l"(p), "f"(a) : "memory");
}
__device__ __forceinline__ void red_add_v2_h2(__half* p, uint32_t a, uint32_t b) {
    asm volatile("red.global.add.noftz.v2.f16x2 [%0], {%1,%2};"
                 :: "l"(p), "r"(a), "r"(b) : "memory");
}

// ---------------- packed f32x2 FMA helpers ----------------
__device__ __forceinline__ unsigned long long pack2(float v) {
    unsigned long long r;
    asm("mov.b64 %0, {%1, %1};" : "=l"(r) : "f"(v));
    return r;
}
__device__ __forceinline__ unsigned long long fma2(unsigned long long a,
                                                   unsigned long long b,
                                                   unsigned long long c) {
    unsigned long long d;
    asm("fma.rn.f32x2 %0, %1, %2, %3;" : "=l"(d) : "l"(a), "l"(b), "l"(c));
    return d;
}
__device__ __forceinline__ void unpack2(unsigned long long p, float& lo, float& hi) {
    asm("mov.b64 {%0, %1}, %2;" : "=f"(lo), "=f"(hi) : "l"(p));
}

// swizzled column-group: physical cg = cg ^ ((row>>2)&15); row stride 64 floats
__device__ __forceinline__ int swidx(int row, int cg, int c) {
    return (row << 6) + (((cg ^ ((row >> 2) & 15)) & 15) << 2) + c;
}

// ---- K=64 GEMM via f32x2, hoisted swizzle (group constant over 4 i's) ----
__device__ __forceinline__ void gemm64_fx2(const float* __restrict__ s_x,
                                           const float* __restrict__ s_w,
                                           int oq, int nq, float acc[4][4]) {
    unsigned long long a2[2][4];
#pragma unroll
    for (int p = 0; p < 2; p++)
#pragma unroll
        for (int k = 0; k < 4; k++) a2[p][k] = 0ull;
#pragma unroll
    for (int i4 = 0; i4 < 16; i4++) {
        const float* xb = &s_x[(i4 << 8) + (((nq ^ i4) & 15) << 2)];
        const float* wb = &s_w[(i4 << 8) + (oq << 2)];
#pragma unroll
        for (int j = 0; j < 4; j++) {
            ulonglong2 xp = *reinterpret_cast<const ulonglong2*>(xb + (j << 6));
            float4 wv = *reinterpret_cast<const float4*>(wb + (j << 6));
            unsigned long long w0 = pack2(wv.x), w1 = pack2(wv.y);
            unsigned long long w2 = pack2(wv.z), w3 = pack2(wv.w);
            a2[0][0] = fma2(xp.x, w0, a2[0][0]);
            a2[0][1] = fma2(xp.x, w1, a2[0][1]);
            a2[0][2] = fma2(xp.x, w2, a2[0][2]);
            a2[0][3] = fma2(xp.x, w3, a2[0][3]);
            a2[1][0] = fma2(xp.y, w0, a2[1][0]);
            a2[1][1] = fma2(xp.y, w1, a2[1][1]);
            a2[1][2] = fma2(xp.y, w2, a2[1][2]);
            a2[1][3] = fma2(xp.y, w3, a2[1][3]);
        }
    }
#pragma unroll
    for (int k = 0; k < 4; k++) {
        unpack2(a2[0][k], acc[0][k], acc[1][k]);
        unpack2(a2[1][k], acc[2][k], acc[3][k]);
    }
}

// ------- BatchNorm statistics: per-block partials (R11 form) -------
__global__ __launch_bounds__(256) void bn_stats_kernel(const float* __restrict__ h,
                                                       float* __restrict__ part) {
    float s[5] = {0, 0, 0, 0, 0}, q[5] = {0, 0, 0, 0, 0};
    int stride = gridDim.x * blockDim.x;
    for (int n = blockIdx.x * blockDim.x + threadIdx.x; n < N_NODES; n += stride) {
#pragma unroll
        for (int i = 0; i < 5; i++) {
            float v = h[n * 5 + i];
            s[i] += v;
            q[i] += v * v;
        }
    }
#pragma unroll
    for (int k = 16; k > 0; k >>= 1) {
#pragma unroll
        for (int i = 0; i < 5; i++) {
            s[i] += __shfl_down_sync(0xffffffffu, s[i], k);
            q[i] += __shfl_down_sync(0xffffffffu, q[i], k);
        }
    }
    __shared__ float sh[10];
    if (threadIdx.x < 10) sh[threadIdx.x] = 0.f;
    __syncthreads();
    if ((threadIdx.x & 31) == 0) {
#pragma unroll
        for (int i = 0; i < 5; i++) {
            atomicAdd(&sh[i], s[i]);
            atomicAdd(&sh[5 + i], q[i]);
        }
    }
    __syncthreads();
    if (threadIdx.x < 10) part[blockIdx.x * 16 + threadIdx.x] = sh[threadIdx.x];
}

// ------- BN apply + conv1 projection (5x5) -> fp16 y8 ; zero agg8 (R11 form) -------
__global__ __launch_bounds__(256) void bn_conv1_kernel(const float* __restrict__ h,
                                                       const float* __restrict__ part,
                                                       const float* __restrict__ gamma,
                                                       const float* __restrict__ beta,
                                                       const float* __restrict__ pw,
                                                       const float* __restrict__ pb,
                                                       float* __restrict__ x0p,
                                                       __half* __restrict__ y8,
                                                       float* __restrict__ agg8) {
    __shared__ float s_warp[8][10];
    __shared__ float s_stats[10];
    int t = threadIdx.x;
    int lane = t & 31, wid = t >> 5;
    {
        float v[10];
#pragma unroll
        for (int i = 0; i < 10; i++) v[i] = 0.f;
        if (t < 148) {
#pragma unroll
            for (int i = 0; i < 10; i++) v[i] = part[t * 16 + i];
        }
#pragma unroll
        for (int k = 16; k > 0; k >>= 1) {
#pragma unroll
            for (int i = 0; i < 10; i++) v[i] += __shfl_down_sync(0xffffffffu, v[i], k);
        }
        if (lane == 0) {
#pragma unroll
            for (int i = 0; i < 10; i++) s_warp[wid][i] = v[i];
        }
    }
    __syncthreads();
    if (t < 10) {
        float acc = 0.f;
#pragma unroll
        for (int w = 0; w < 8; w++) acc += s_warp[w][t];
        s_stats[t] = acc;
    }
    __syncthreads();

    int n = blockIdx.x * blockDim.x + t;
    if (n >= N_NODES) return;
    const float inv_n = 1.f / (float)N_NODES;
    float xr[5];
#pragma unroll
    for (int i = 0; i < 5; i++) {
        float mu = s_stats[i] * inv_n;
        float var = s_stats[5 + i] * inv_n - mu * mu;
        float sc = rsqrtf(var + EPS_BN) * gamma[i];
        xr[i] = (h[n * 5 + i] - mu) * sc + beta[i];
    }
    float4* x0v = reinterpret_cast<float4*>(x0p + (size_t)n * 8);
    x0v[0] = make_float4(xr[0], xr[1], xr[2], xr[3]);
    x0v[1] = make_float4(xr[4], 0.f, 0.f, 0.f);
    float xp[5];
#pragma unroll
    for (int k = 0; k < 5; k++) {
        float v = pb[k];
#pragma unroll
        for (int i = 0; i < 5; i++) v += xr[i] * pw[i * 5 + k];
        xp[k] = fmaxf(v, 0.f);
    }
    __half2 h0 = __floats2half2_rn(xp[0], xp[1]);
    __half2 h1 = __floats2half2_rn(xp[2], xp[3]);
    __half2 h2 = __floats2half2_rn(xp[4], 0.f);
    uint4 pack;
    pack.x = *reinterpret_cast<uint32_t*>(&h0);
    pack.y = *reinterpret_cast<uint32_t*>(&h1);
    pack.z = *reinterpret_cast<uint32_t*>(&h2);
    pack.w = 0u;
    *reinterpret_cast<uint4*>(y8 + (size_t)n * 8) = pack;
    float4* av = reinterpret_cast<float4*>(agg8 + (size_t)n * 8);
    float4 z = make_float4(0.f, 0.f, 0.f, 0.f);
    av[0] = z;
    av[1] = z;
}

// -------- width-8 push scatter (one edge per thread) --------
template <bool ADD_CNT>
__global__ void scatter8_kernel(const int* __restrict__ src,
                                const int* __restrict__ dst,
                                const float* __restrict__ ew,
                                const __half* __restrict__ y8,
                                float* __restrict__ agg8) {
    int stride = gridDim.x * blockDim.x;
    for (int e = blockIdx.x * blockDim.x + threadIdx.x; e < N_EDGES; e += stride) {
        int s = __ldg(&src[e]);
        int d = __ldg(&dst[e]);
        float w = __ldg(&ew[e]);
        uint4 raw = *reinterpret_cast<const uint4*>(y8 + (size_t)s * 8);
        float2 f0 = __half22float2(*reinterpret_cast<__half2*>(&raw.x));
        float2 f1 = __half22float2(*reinterpret_cast<__half2*>(&raw.y));
        float2 f2 = __half22float2(*reinterpret_cast<__half2*>(&raw.z));
        red_add_v4(agg8 + (size_t)d * 8,
                   make_float4(f0.x * w, f0.y * w, f1.x * w, f1.y * w));
        if (ADD_CNT)
            red_add_v2(agg8 + (size_t)d * 8 + 4, f2.x * w, 1.0f);
        else
            red_add_f32(agg8 + (size_t)d * 8 + 4, f2.x * w);
    }
}

// -------- width-64 push scatter: fp16 reads AND fp16 atomics --------
__global__ void scatter64_kernel(const int* __restrict__ src,
                                 const int* __restrict__ dst,
                                 const float* __restrict__ ew,
                                 const __half* __restrict__ y,
                                 __half* __restrict__ agg) {
    int lane = threadIdx.x & 31;
    int warp = (blockIdx.x * blockDim.x + threadIdx.x) >> 5;
    int nwarps = (gridDim.x * blockDim.x) >> 5;
    int half = lane >> 4;
    int fq = (lane & 15) << 2;
    const int npairs = N_EDGES / 2;
    for (int p = warp; p < npairs; p += nwarps) {
        int e = 2 * p + half;
        int s = __ldg(&src[e]);
        int d = __ldg(&dst[e]);
        float w = __ldg(&ew[e]);
        uint2 raw = *reinterpret_cast<const uint2*>(y + (size_t)s * 64 + fq);
        float2 f0 = __half22float2(*reinterpret_cast<__half2*>(&raw.x));
        float2 f1 = __half22float2(*reinterpret_cast<__half2*>(&raw.y));
        __half2 h0 = __floats2half2_rn(f0.x * w, f0.y * w);
        __half2 h1 = __floats2half2_rn(f1.x * w, f1.y * w);
        red_add_v2_h2(agg + (size_t)d * 64 + fq,
                      *reinterpret_cast<uint32_t*>(&h0),
                      *reinterpret_cast<uint32_t*>(&h1));
    }
}

// ==================== fp1: conv1 finalize + conv2 projection ====================
__global__ __launch_bounds__(256) void fp1_kernel(const float* __restrict__ x0p,
                                                  const float* __restrict__ agg8,
                                                  const float* __restrict__ lw1,
                                                  const float* __restrict__ lb1,
                                                  const float* __restrict__ rw1,
                                                  const float* __restrict__ pw2,
                                                  const float* __restrict__ pb2,
                                                  const float* __restrict__ lw2,
                                                  float* __restrict__ x1,
                                                  float* __restrict__ cinv_out,
                                                  __half* __restrict__ y,
                                                  __half* __restrict__ aggh_zero) {
    __shared__ float s_w[64 * 64];
    __shared__ float s_x[64 * 64];
    __shared__ float s_b[64];
    __shared__ float s_ci[64];
    const int t = threadIdx.x;
    const int n0 = blockIdx.x * 64;
    const int oq = t & 15, nq = t >> 4;

    {
        float4 z = make_float4(0.f, 0.f, 0.f, 0.f);
        float4* zb = reinterpret_cast<float4*>(aggh_zero);
        int base = blockIdx.x * 512;
        for (int i = t; i < 512; i += 256) {
            int gi = base + i;
            if (gi < N_NODES * 8) zb[gi] = z;
        }
    }

    for (int idx = t; idx < 640; idx += 256)
        s_w[idx] = (idx < 320) ? lw1[idx] : rw1[idx - 320];
    if (t < 64) s_b[t] = lb1[t];
    if (t < 64) {
        int nn = min(n0 + t, N_NODES - 1);
        float c = agg8[(size_t)nn * 8 + 5];
        float ci = 1.f / fmaxf(c, 1.f);
        s_ci[t] = ci;
        if (n0 + t < N_NODES) cinv_out[n0 + t] = ci;
    }
    __syncthreads();
    for (int idx = t; idx < 640; idx += 256) {
        int i = idx >> 6, nd = idx & 63;
        int nn = min(n0 + nd, N_NODES - 1);
        s_x[i * 72 + nd] = (i < 5) ? agg8[(size_t)nn * 8 + i] * s_ci[nd]
                                   : x0p[(size_t)nn * 8 + (i - 5)];
    }
    __syncthreads();

    // ---- GEMM0: K=10 (scalar) ----
    float acc[4][4];
#pragma unroll
    for (int a = 0; a < 4; a++)
#pragma unroll
        for (int b = 0; b < 4; b++) acc[a][b] = 0.f;
#pragma unroll
    for (int i = 0; i < 10; i++) {
        float4 xv = *reinterpret_cast<const float4*>(&s_x[i * 72 + (nq << 2)]);
        float4 wv = *reinterpret_cast<const float4*>(&s_w[(i << 6) + (oq << 2)]);
        acc[0][0] += xv.x * wv.x; acc[0][1] += xv.x * wv.y; acc[0][2] += xv.x * wv.z; acc[0][3] += xv.x * wv.w;
        acc[1][0] += xv.y * wv.x; acc[1][1] += xv.y * wv.y; acc[1][2] += xv.y * wv.z; acc[1][3] += xv.y * wv.w;
        acc[2][0] += xv.z * wv.x; acc[2][1] += xv.z * wv.y; acc[2][2] += xv.z * wv.z; acc[2][3] += xv.z * wv.w;
        acc[3][0] += xv.w * wv.x; acc[3][1] += xv.w * wv.y; acc[3][2] += xv.w * wv.z; acc[3][3] += xv.w * wv.w;
    }
    float lb0 = s_b[(oq << 2) + 0], lb1v = s_b[(oq << 2) + 1];
    float lb2 = s_b[(oq << 2) + 2], lb3 = s_b[(oq << 2) + 3];
#pragma unroll
    for (int dn = 0; dn < 4; dn++) {
        float v0 = acc[dn][0] + lb0;
        float v1 = acc[dn][1] + lb1v;
        float v2 = acc[dn][2] + lb2;
        float v3 = acc[dn][3] + lb3;
        float ss = v0 * v0 + v1 * v1 + v2 * v2 + v3 * v3;
        ss += __shfl_down_sync(0xffffffffu, ss, 8, 16);
        ss += __shfl_down_sync(0xffffffffu, ss, 4, 16);
        ss += __shfl_down_sync(0xffffffffu, ss, 2, 16);
        ss += __shfl_down_sync(0xffffffffu, ss, 1, 16);
        ss = __shfl_sync(0xffffffffu, ss, 0, 16);
        float sc = 1.f / fmaxf(sqrtf(ss), EPS_NORM);
        acc[dn][0] = fmaxf(v0 * sc, 0.f);
        acc[dn][1] = fmaxf(v1 * sc, 0.f);
        acc[dn][2] = fmaxf(v2 * sc, 0.f);
        acc[dn][3] = fmaxf(v3 * sc, 0.f);
    }
    __syncthreads();

#pragma unroll
    for (int dn = 0; dn < 4; dn++) {
        int n = n0 + (nq << 2) + dn;
        if (n < N_NODES) {
            *reinterpret_cast<float4*>(&x1[(size_t)n * 64 + (oq << 2)]) =
                make_float4(acc[dn][0], acc[dn][1], acc[dn][2], acc[dn][3]);
        }
#pragma unroll
        for (int dk = 0; dk < 4; dk++)
            s_x[swidx((oq << 2) + dk, nq, dn)] = acc[dn][dk];
    }
    for (int i4 = t; i4 < 1024; i4 += 256)
        reinterpret_cast<float4*>(s_w)[i4] = reinterpret_cast<const float4*>(pw2)[i4];
    if (t < 64) s_b[t] = pb2[t];
    __syncthreads();

    // ---- GEMM1: K=64 (f32x2, hoisted) ----
    gemm64_fx2(s_x, s_w, oq, nq, acc);
    __syncthreads();
#pragma unroll
    for (int dk = 0; dk < 4; dk++) {
        float b = s_b[(oq << 2) + dk];
#pragma unroll
        for (int dn = 0; dn < 4; dn++)
            s_x[swidx((oq << 2) + dk, nq, dn)] = fmaxf(acc[dn][dk] + b, 0.f);
    }
    for (int i4 = t; i4 < 1024; i4 += 256)
        reinterpret_cast<float4*>(s_w)[i4] = reinterpret_cast<const float4*>(lw2)[i4];
    __syncthreads();

    // ---- GEMM2: K=64 (f32x2, hoisted) -> y fp16 ----
    gemm64_fx2(s_x, s_w, oq, nq, acc);
#pragma unroll
    for (int dn = 0; dn < 4; dn++) {
        int n = n0 + (nq << 2) + dn;
        if (n < N_NODES) {
            __half2 h0 = __floats2half2_rn(acc[dn][0], acc[dn][1]);
            __half2 h1 = __floats2half2_rn(acc[dn][2], acc[dn][3]);
            uint2 pack;
            pack.x = *reinterpret_cast<uint32_t*>(&h0);
            pack.y = *reinterpret_cast<uint32_t*>(&h1);
            *reinterpret_cast<uint2*>(y + (size_t)n * 64 + (oq << 2)) = pack;
        }
    }
}

// ==================== fp2: conv2 finalize + conv3 projection ====================
__global__ __launch_bounds__(256) void fp2_kernel(const float* __restrict__ x1,
                                                  const __half* __restrict__ agg,
                                                  const float* __restrict__ cinv,
                                                  const float* __restrict__ rw2,
                                                  const float* __restrict__ lb2,
                                                  const float* __restrict__ pw3,
                                                  const float* __restrict__ pb3,
                                                  const float* __restrict__ lw3,
                                                  float* __restrict__ x2,
                                                  __half* __restrict__ y8,
                                                  float* __restrict__ agg8z) {
    __shared__ float s_w[64 * 64];
    __shared__ float s_x[64 * 64];
    __shared__ float s_b[64];
    const int t = threadIdx.x;
    const int n0 = blockIdx.x * 64;
    const int oq = t & 15, nq = t >> 4;

    if (t < 128) {
        int gi = blockIdx.x * 128 + t;
        if (gi < N_NODES * 2) {
            float4 z = make_float4(0.f, 0.f, 0.f, 0.f);
            reinterpret_cast<float4*>(agg8z)[gi] = z;
        }
    }

    for (int i4 = t; i4 < 1024; i4 += 256)
        reinterpret_cast<float4*>(s_w)[i4] = reinterpret_cast<const float4*>(rw2)[i4];
    if (t < 64) s_b[t] = lb2[t];
    for (int idx = t; idx < 64 * 64; idx += 256) {
        int n = idx >> 6, i = idx & 63;
        int nn = min(n0 + n, N_NODES - 1);
        s_x[swidx(i, n >> 2, n & 3)] = x1[(size_t)nn * 64 + i];
    }
    __syncthreads();

    // ---- GEMM0: root term (f32x2, hoisted) ----
    float acc[4][4];
    gemm64_fx2(s_x, s_w, oq, nq, acc);

    float lb0 = s_b[(oq << 2) + 0], lb1v = s_b[(oq << 2) + 1];
    float lb2v = s_b[(oq << 2) + 2], lb3 = s_b[(oq << 2) + 3];
#pragma unroll
    for (int dn = 0; dn < 4; dn++) {
        int n = n0 + (nq << 2) + dn;
        int nn = min(n, N_NODES - 1);
        float ci = cinv[nn];
        uint2 raw = *reinterpret_cast<const uint2*>(agg + (size_t)nn * 64 + (oq << 2));
        float2 g0 = __half22float2(*reinterpret_cast<__half2*>(&raw.x));
        float2 g1 = __half22float2(*reinterpret_cast<__half2*>(&raw.y));
        float v0 = acc[dn][0] + lb0 + g0.x * ci;
        float v1 = acc[dn][1] + lb1v + g0.y * ci;
        float v2 = acc[dn][2] + lb2v + g1.x * ci;
        float v3 = acc[dn][3] + lb3 + g1.y * ci;
        float ss = v0 * v0 + v1 * v1 + v2 * v2 + v3 * v3;
        ss += __shfl_down_sync(0xffffffffu, ss, 8, 16);
        ss += __shfl_down_sync(0xffffffffu, ss, 4, 16);
        ss += __shfl_down_sync(0xffffffffu, ss, 2, 16);
        ss += __shfl_down_sync(0xffffffffu, ss, 1, 16);
        ss = __shfl_sync(0xffffffffu, ss, 0, 16);
        float sc = 1.f / fmaxf(sqrtf(ss), EPS_NORM);
        acc[dn][0] = fmaxf(v0 * sc, 0.f);
        acc[dn][1] = fmaxf(v1 * sc, 0.f);
        acc[dn][2] = fmaxf(v2 * sc, 0.f);
        acc[dn][3] = fmaxf(v3 * sc, 0.f);
    }
    __syncthreads();

#pragma unroll
    for (int dn = 0; dn < 4; dn++) {
        int n = n0 + (nq << 2) + dn;
        if (n < N_NODES) {
            *reinterpret_cast<float4*>(&x2[(size_t)n * 64 + (oq << 2)]) =
                make_float4(acc[dn][0], acc[dn][1], acc[dn][2], acc[dn][3]);
        }
#pragma unroll
        for (int dk = 0; dk < 4; dk++)
            s_x[swidx((oq << 2) + dk, nq, dn)] = acc[dn][dk];
    }
    for (int i4 = t; i4 < 1024; i4 += 256)
        reinterpret_cast<float4*>(s_w)[i4] = reinterpret_cast<const float4*>(pw3)[i4];
    if (t < 64) s_b[t] = pb3[t];
    __syncthreads();

    // ---- GEMM1: xp = relu(x2 @ pw3 + pb3) (f32x2, hoisted) ----
    gemm64_fx2(s_x, s_w, oq, nq, acc);
    __syncthreads();
#pragma unroll
    for (int dk = 0; dk < 4; dk++) {
        float b = s_b[(oq << 2) + dk];
#pragma unroll
        for (int dn = 0; dn < 4; dn++)
            s_x[swidx((oq << 2) + dk, nq, dn)] = fmaxf(acc[dn][dk] + b, 0.f);
    }
    for (int idx = t; idx < 64 * 8; idx += 256) s_w[idx] = 0.f;
    __syncthreads();
    for (int idx = t; idx < 64 * 5; idx += 256) s_w[(idx / 5) * 8 + (idx % 5)] = lw3[idx];
    __syncthreads();

    // ---- GEMM2: y8 = xp @ lw3 (OUTP=8, scalar, hoisted swizzle) ----
    if (oq < 2) {
        float a2[4][4];
#pragma unroll
        for (int a = 0; a < 4; a++)
#pragma unroll
            for (int b = 0; b < 4; b++) a2[a][b] = 0.f;
#pragma unroll
        for (int i4 = 0; i4 < 16; i4++) {
            const float* xb = &s_x[(i4 << 8) + (((nq ^ i4) & 15) << 2)];
            const float* wb = &s_w[(i4 << 5) + (oq << 2)];
#pragma unroll
            for (int j = 0; j < 4; j++) {
                float4 xv = *reinterpret_cast<const float4*>(xb + (j << 6));
                float4 wv = *reinterpret_cast<const float4*>(wb + (j << 3));
                a2[0][0] += xv.x * wv.x; a2[0][1] += xv.x * wv.y; a2[0][2] += xv.x * wv.z; a2[0][3] += xv.x * wv.w;
                a2[1][0] += xv.y * wv.x; a2[1][1] += xv.y * wv.y; a2[1][2] += xv.y * wv.z; a2[1][3] += xv.y * wv.w;
                a2[2][0] += xv.z * wv.x; a2[2][1] += xv.z * wv.y; a2[2][2] += xv.z * wv.z; a2[2][3] += xv.z * wv.w;
                a2[3][0] += xv.w * wv.x; a2[3][1] += xv.w * wv.y; a2[3][2] += xv.w * wv.z; a2[3][3] += xv.w * wv.w;
            }
        }
#pragma unroll
        for (int dn = 0; dn < 4; dn++) {
            int n = n0 + (nq << 2) + dn;
            if (n < N_NODES) {
                __half2 h0 = __floats2half2_rn(a2[dn][0], a2[dn][1]);
                __half2 h1 = __floats2half2_rn(a2[dn][2], a2[dn][3]);
                uint2 pack;
                pack.x = *reinterpret_cast<uint32_t*>(&h0);
                pack.y = *reinterpret_cast<uint32_t*>(&h1);
                *reinterpret_cast<uint2*>(y8 + (size_t)n * 8 + (oq << 2)) = pack;
            }
        }
    }
}

// ------- conv3 finalize: out5 = agg*cinv + lb + x2@rw ; norm (no relu) -------
__global__ __launch_bounds__(128) void fin3_kernel(const float* __restrict__ x2,
                                                   const float* __restrict__ agg8,
                                                   const float* __restrict__ cinv,
                                                   const float* __restrict__ rw,
                                                   const float* __restrict__ lb,
                                                   float* __restrict__ out) {
    __shared__ float s_rw[64 * 8];
    __shared__ float s_lb[8];
    int t = threadIdx.x;
    for (int idx = t; idx < 320; idx += 128) s_rw[(idx / 5) * 8 + (idx % 5)] = rw[idx];
    if (t < 5) s_lb[t] = lb[t];
    __syncthreads();
    int n = blockIdx.x * 128 + t;
    if (n >= N_NODES) return;

    float ci = cinv[n];
    const float4* av = reinterpret_cast<const float4*>(agg8 + (size_t)n * 8);
    float4 a0 = av[0], a1 = av[1];
    float4 vf = make_float4(s_lb[0] + a0.x * ci, s_lb[1] + a0.y * ci,
                            s_lb[2] + a0.z * ci, s_lb[3] + a0.w * ci);
    float v4 = s_lb[4] + a1.x * ci;

    const float4* xr = reinterpret_cast<const float4*>(x2 + (size_t)n * 64);
#pragma unroll
    for (int iq = 0; iq < 16; iq++) {
        float4 xv = xr[iq];
        float xs[4] = {xv.x, xv.y, xv.z, xv.w};
#pragma unroll
        for (int c = 0; c < 4; c++) {
            int i = iq * 4 + c;
            float4 w = *reinterpret_cast<const float4*>(&s_rw[i * 8]);
            float w4 = s_rw[i * 8 + 4];
            vf.x += xs[c] * w.x;
            vf.y += xs[c] * w.y;
            vf.z += xs[c] * w.z;
            vf.w += xs[c] * w.w;
            v4 += xs[c] * w4;
        }
    }
    float ss = vf.x * vf.x + vf.y * vf.y + vf.z * vf.z + vf.w * vf.w + v4 * v4;
    float sc = 1.f / fmaxf(sqrtf(ss), EPS_NORM);
    float* o = out + (size_t)n * 5;
    o[0] = vf.x * sc;
    o[1] = vf.y * sc;
    o[2] = vf.z * sc;
    o[3] = vf.w * sc;
    o[4] = v4 * sc;
}

// ---------------- host launcher ----------------
extern "C" void kernel_launch(void* const* d_in, const int* in_sizes, int n_in,
                              void* d_out, int out_size) {
    const float* h = (const float*)d_in[0];
    const int* ei = (const int*)d_in[1];
    const float* ew = (const float*)d_in[2];
    const float* gamma = (const float*)d_in[3];
    const float* beta = (const float*)d_in[4];
    const float* c1_pw = (const float*)d_in[5];
    const float* c1_pb = (const float*)d_in[6];
    const float* c1_lw = (const float*)d_in[7];
    const float* c1_lb = (const float*)d_in[8];
    const float* c1_rw = (const float*)d_in[9];
    const float* c2_pw = (const float*)d_in[10];
    const float* c2_pb = (const float*)d_in[11];
    const float* c2_lw = (const float*)d_in[12];
    const float* c2_lb = (const float*)d_in[13];
    const float* c2_rw = (const float*)d_in[14];
    const float* c3_pw = (const float*)d_in[15];
    const float* c3_pb = (const float*)d_in[16];
    const float* c3_lw = (const float*)d_in[17];
    const float* c3_lb = (const float*)d_in[18];
    const float* c3_rw = (const float*)d_in[19];
    float* out = (float*)d_out;

    const int* src = ei;
    const int* dst = ei + N_EDGES;

    float *x0, *x1, *x2, *agg8, *cinv, *part;
    __half *yh, *aggh;
    cudaGetSymbolAddress((void**)&x0, g_x0);
    cudaGetSymbolAddress((void**)&x1, g_x1);
    cudaGetSymbolAddress((void**)&x2, g_x2);
    cudaGetSymbolAddress((void**)&yh, g_yh);
    cudaGetSymbolAddress((void**)&aggh, g_aggh);
    cudaGetSymbolAddress((void**)&agg8, g_agg8);
    cudaGetSymbolAddress((void**)&cinv, g_cinv);
    cudaGetSymbolAddress((void**)&part, g_part);

    const int NB64 = (N_NODES + 63) / 64;   // 1563

    // 1: BN partial stats (R11 form)
    bn_stats_kernel<<<148, 256>>>(h, part);
    // 2: BN apply + conv1 5x5 projection (R11 form); zeroes agg8
    bn_conv1_kernel<<<(N_NODES + 255) / 256, 256>>>(h, part, gamma, beta, c1_pw, c1_pb,
                                                    x0, yh, agg8);
    // 3: conv1 push-scatter (width 5 + cnt)
    scatter8_kernel<true><<<6250, 256>>>(src, dst, ew, yh, agg8);
    // 4: FUSED conv1-finalize + conv2-projection — CAPTURED BY NCU
    fp1_kernel<<<NB64, 256>>>(x0, agg8, c1_lw, c1_lb, c1_rw,
                              c2_pw, c2_pb, c2_lw, x1, cinv, yh, aggh);
    // 5: conv2 push-scatter (fp16 atomics)
    scatter64_kernel<<<4096, 256>>>(src, dst, ew, yh, aggh);
    // 6: FUSED conv2-finalize + conv3-projection (zeroes agg8)
    fp2_kernel<<<NB64, 256>>>(x1, aggh, cinv, c2_rw, c2_lb,
                              c3_pw, c3_pb, c3_lw, x2, yh, agg8);
    // 7: conv3 push-scatter (width 5)
    scatter8_kernel<false><<<6250, 256>>>(src, dst, ew, yh, agg8);
    // 8: conv3 finalize
    fin3_kernel<<<(N_NODES + 127) / 128, 128>>>(x2, agg8, cinv, c3_rw, c3_lb, out);
}

// round 14
// speedup vs baseline: 1.0389x; 1.0389x over previous
#include <cuda_runtime.h>
#include <cuda_fp16.h>
#include <cstdint>
#include <math.h>

#define N_NODES 100000
#define N_EDGES 3200000
#define EPS_BN 1e-5f
#define EPS_NORM 1e-12f

// ---------------- device scratch (no allocation allowed) ----------------
__device__ __align__(16) float g_x0[N_NODES * 8];     // BN output (padded stride 8)
__device__ __align__(16) float g_x1[N_NODES * 64];    // conv1 output
__device__ __align__(16) float g_x2[N_NODES * 64];    // conv2 output
__device__ __align__(16) __half g_yh[N_NODES * 64];   // fp16 projected features (stride 64 or 8)
__device__ __align__(16) __half g_aggh[N_NODES * 64]; // conv2 accumulator (fp16 atomics)
__device__ __align__(32) float g_agg8[N_NODES * 8];   // conv1/conv3 accumulator (5 feats + cnt)
__device__ float g_cinv[N_NODES];                     // 1/max(cnt,1)
__device__ __align__(16) float g_part[148 * 16];      // BN per-block partials

// ---------------- vector reductions ----------------
__device__ __forceinline__ void red_add_v4(float* p, float4 v) {
    asm volatile("red.global.add.v4.f32 [%0], {%1,%2,%3,%4};"
                 :: "l"(p), "f"(v.x), "f"(v.y), "f"(v.z), "f"(v.w) : "memory");
}
__device__ __forceinline__ void red_add_v2(float* p, float a, float b) {
    asm volatile("red.global.add.v2.f32 [%0], {%1,%2};"
                 :: "l"(p), "f"(a), "f"(b) : "memory");
}
__device__ __forceinline__ void red_add_f32(float* p, float a) {
    asm volatile("red.global.add.f32 [%0], %1;"
                 :: "l"(p), "f"(a) : "memory");
}
__device__ __forceinline__ void red_add_v4_h2(__half* p, uint32_t a, uint32_t b,
                                              uint32_t c, uint32_t d) {
    asm volatile("red.global.add.noftz.v4.f16x2 [%0], {%1,%2,%3,%4};"
                 :: "l"(p), "r"(a), "r"(b), "r"(c), "r"(d) : "memory");
}

// ---------------- packed f32x2 FMA helpers ----------------
__device__ __forceinline__ unsigned long long pack2(float v) {
    unsigned long long r;
    asm("mov.b64 %0, {%1, %1};" : "=l"(r) : "f"(v));
    return r;
}
__device__ __forceinline__ unsigned long long fma2(unsigned long long a,
                                                   unsigned long long b,
                                                   unsigned long long c) {
    unsigned long long d;
    asm("fma.rn.f32x2 %0, %1, %2, %3;" : "=l"(d) : "l"(a), "l"(b), "l"(c));
    return d;
}
__device__ __forceinline__ void unpack2(unsigned long long p, float& lo, float& hi) {
    asm("mov.b64 {%0, %1}, %2;" : "=f"(lo), "=f"(hi) : "l"(p));
}

// swizzled column-group: physical cg = cg ^ ((row>>2)&15); row stride 64 floats
__device__ __forceinline__ int swidx(int row, int cg, int c) {
    return (row << 6) + (((cg ^ ((row >> 2) & 15)) & 15) << 2) + c;
}

// ---- K=64 GEMM via f32x2, hoisted swizzle (group constant over 4 i's) ----
__device__ __forceinline__ void gemm64_fx2(const float* __restrict__ s_x,
                                           const float* __restrict__ s_w,
                                           int oq, int nq, float acc[4][4]) {
    unsigned long long a2[2][4];
#pragma unroll
    for (int p = 0; p < 2; p++)
#pragma unroll
        for (int k = 0; k < 4; k++) a2[p][k] = 0ull;
#pragma unroll
    for (int i4 = 0; i4 < 16; i4++) {
        const float* xb = &s_x[(i4 << 8) + (((nq ^ i4) & 15) << 2)];
        const float* wb = &s_w[(i4 << 8) + (oq << 2)];
#pragma unroll
        for (int j = 0; j < 4; j++) {
            ulonglong2 xp = *reinterpret_cast<const ulonglong2*>(xb + (j << 6));
            float4 wv = *reinterpret_cast<const float4*>(wb + (j << 6));
            unsigned long long w0 = pack2(wv.x), w1 = pack2(wv.y);
            unsigned long long w2 = pack2(wv.z), w3 = pack2(wv.w);
            a2[0][0] = fma2(xp.x, w0, a2[0][0]);
            a2[0][1] = fma2(xp.x, w1, a2[0][1]);
            a2[0][2] = fma2(xp.x, w2, a2[0][2]);
            a2[0][3] = fma2(xp.x, w3, a2[0][3]);
            a2[1][0] = fma2(xp.y, w0, a2[1][0]);
            a2[1][1] = fma2(xp.y, w1, a2[1][1]);
            a2[1][2] = fma2(xp.y, w2, a2[1][2]);
            a2[1][3] = fma2(xp.y, w3, a2[1][3]);
        }
    }
#pragma unroll
    for (int k = 0; k < 4; k++) {
        unpack2(a2[0][k], acc[0][k], acc[1][k]);
        unpack2(a2[1][k], acc[2][k], acc[3][k]);
    }
}

// ------- BatchNorm statistics: per-block partials -------
__global__ __launch_bounds__(256) void bn_stats_kernel(const float* __restrict__ h,
                                                       float* __restrict__ part) {
    float s[5] = {0, 0, 0, 0, 0}, q[5] = {0, 0, 0, 0, 0};
    int stride = gridDim.x * blockDim.x;
    for (int n = blockIdx.x * blockDim.x + threadIdx.x; n < N_NODES; n += stride) {
#pragma unroll
        for (int i = 0; i < 5; i++) {
            float v = h[n * 5 + i];
            s[i] += v;
            q[i] += v * v;
        }
    }
#pragma unroll
    for (int k = 16; k > 0; k >>= 1) {
#pragma unroll
        for (int i = 0; i < 5; i++) {
            s[i] += __shfl_down_sync(0xffffffffu, s[i], k);
            q[i] += __shfl_down_sync(0xffffffffu, q[i], k);
        }
    }
    __shared__ float sh[10];
    if (threadIdx.x < 10) sh[threadIdx.x] = 0.f;
    __syncthreads();
    if ((threadIdx.x & 31) == 0) {
#pragma unroll
        for (int i = 0; i < 5; i++) {
            atomicAdd(&sh[i], s[i]);
            atomicAdd(&sh[5 + i], q[i]);
        }
    }
    __syncthreads();
    if (threadIdx.x < 10) part[blockIdx.x * 16 + threadIdx.x] = sh[threadIdx.x];
}

// ------- BN apply + conv1 projection (5x5) -> fp16 y8 ; zero agg8 -------
__global__ __launch_bounds__(256) void bn_conv1_kernel(const float* __restrict__ h,
                                                       const float* __restrict__ part,
                                                       const float* __restrict__ gamma,
                                                       const float* __restrict__ beta,
                                                       const float* __restrict__ pw,
                                                       const float* __restrict__ pb,
                                                       float* __restrict__ x0p,
                                                       __half* __restrict__ y8,
                                                       float* __restrict__ agg8) {
    __shared__ float s_warp[8][10];
    __shared__ float s_stats[10];
    int t = threadIdx.x;
    int lane = t & 31, wid = t >> 5;
    {
        float v[10];
#pragma unroll
        for (int i = 0; i < 10; i++) v[i] = 0.f;
        if (t < 148) {
#pragma unroll
            for (int i = 0; i < 10; i++) v[i] = part[t * 16 + i];
        }
#pragma unroll
        for (int k = 16; k > 0; k >>= 1) {
#pragma unroll
            for (int i = 0; i < 10; i++) v[i] += __shfl_down_sync(0xffffffffu, v[i], k);
        }
        if (lane == 0) {
#pragma unroll
            for (int i = 0; i < 10; i++) s_warp[wid][i] = v[i];
        }
    }
    __syncthreads();
    if (t < 10) {
        float acc = 0.f;
#pragma unroll
        for (int w = 0; w < 8; w++) acc += s_warp[w][t];
        s_stats[t] = acc;
    }
    __syncthreads();

    int n = blockIdx.x * blockDim.x + t;
    if (n >= N_NODES) return;
    const float inv_n = 1.f / (float)N_NODES;
    float xr[5];
#pragma unroll
    for (int i = 0; i < 5; i++) {
        float mu = s_stats[i] * inv_n;
        float var = s_stats[5 + i] * inv_n - mu * mu;
        float sc = rsqrtf(var + EPS_BN) * gamma[i];
        xr[i] = (h[n * 5 + i] - mu) * sc + beta[i];
    }
    float4* x0v = reinterpret_cast<float4*>(x0p + (size_t)n * 8);
    x0v[0] = make_float4(xr[0], xr[1], xr[2], xr[3]);
    x0v[1] = make_float4(xr[4], 0.f, 0.f, 0.f);
    float xp[5];
#pragma unroll
    for (int k = 0; k < 5; k++) {
        float v = pb[k];
#pragma unroll
        for (int i = 0; i < 5; i++) v += xr[i] * pw[i * 5 + k];
        xp[k] = fmaxf(v, 0.f);
    }
    __half2 h0 = __floats2half2_rn(xp[0], xp[1]);
    __half2 h1 = __floats2half2_rn(xp[2], xp[3]);
    __half2 h2 = __floats2half2_rn(xp[4], 0.f);
    uint4 pack;
    pack.x = *reinterpret_cast<uint32_t*>(&h0);
    pack.y = *reinterpret_cast<uint32_t*>(&h1);
    pack.z = *reinterpret_cast<uint32_t*>(&h2);
    pack.w = 0u;
    *reinterpret_cast<uint4*>(y8 + (size_t)n * 8) = pack;
    float4* av = reinterpret_cast<float4*>(agg8 + (size_t)n * 8);
    float4 z = make_float4(0.f, 0.f, 0.f, 0.f);
    av[0] = z;
    av[1] = z;
}

// -------- width-8 push scatter (one edge per thread) --------
template <bool ADD_CNT>
__global__ void scatter8_kernel(const int* __restrict__ src,
                                const int* __restrict__ dst,
                                const float* __restrict__ ew,
                                const __half* __restrict__ y8,
                                float* __restrict__ agg8) {
    int stride = gridDim.x * blockDim.x;
    for (int e = blockIdx.x * blockDim.x + threadIdx.x; e < N_EDGES; e += stride) {
        int s = __ldg(&src[e]);
        int d = __ldg(&dst[e]);
        float w = __ldg(&ew[e]);
        uint4 raw = *reinterpret_cast<const uint4*>(y8 + (size_t)s * 8);
        float2 f0 = __half22float2(*reinterpret_cast<__half2*>(&raw.x));
        float2 f1 = __half22float2(*reinterpret_cast<__half2*>(&raw.y));
        float2 f2 = __half22float2(*reinterpret_cast<__half2*>(&raw.z));
        red_add_v4(agg8 + (size_t)d * 8,
                   make_float4(f0.x * w, f0.y * w, f1.x * w, f1.y * w));
        if (ADD_CNT)
            red_add_v2(agg8 + (size_t)d * 8 + 4, f2.x * w, 1.0f);
        else
            red_add_f32(agg8 + (size_t)d * 8 + 4, f2.x * w);
    }
}

// -------- width-64 push scatter: 8 lanes/edge, v4.f16x2 atomics --------
__global__ void scatter64_kernel(const int* __restrict__ src,
                                 const int* __restrict__ dst,
                                 const float* __restrict__ ew,
                                 const __half* __restrict__ y,
                                 __half* __restrict__ agg) {
    int lane = threadIdx.x & 31;
    int warp = (blockIdx.x * blockDim.x + threadIdx.x) >> 5;
    int nwarps = (gridDim.x * blockDim.x) >> 5;
    int quarter = lane >> 3;      // which edge of the group of 4
    int fo = (lane & 7) << 3;     // feature offset (8 halves = 16B)
    const int ngroups = N_EDGES / 4;
    for (int p = warp; p < ngroups; p += nwarps) {
        int e = 4 * p + quarter;
        int s = __ldg(&src[e]);
        int d = __ldg(&dst[e]);
        float w = __ldg(&ew[e]);
        uint4 raw = *reinterpret_cast<const uint4*>(y + (size_t)s * 64 + fo);
        float2 f0 = __half22float2(*reinterpret_cast<__half2*>(&raw.x));
        float2 f1 = __half22float2(*reinterpret_cast<__half2*>(&raw.y));
        float2 f2 = __half22float2(*reinterpret_cast<__half2*>(&raw.z));
        float2 f3 = __half22float2(*reinterpret_cast<__half2*>(&raw.w));
        __half2 h0 = __floats2half2_rn(f0.x * w, f0.y * w);
        __half2 h1 = __floats2half2_rn(f1.x * w, f1.y * w);
        __half2 h2 = __floats2half2_rn(f2.x * w, f2.y * w);
        __half2 h3 = __floats2half2_rn(f3.x * w, f3.y * w);
        red_add_v4_h2(agg + (size_t)d * 64 + fo,
                      *reinterpret_cast<uint32_t*>(&h0),
                      *reinterpret_cast<uint32_t*>(&h1),
                      *reinterpret_cast<uint32_t*>(&h2),
                      *reinterpret_cast<uint32_t*>(&h3));
    }
}

// ==================== fp1: conv1 finalize + conv2 projection ====================
__global__ __launch_bounds__(256) void fp1_kernel(const float* __restrict__ x0p,
                                                  const float* __restrict__ agg8,
                                                  const float* __restrict__ lw1,
                                                  const float* __restrict__ lb1,
                                                  const float* __restrict__ rw1,
                                                  const float* __restrict__ pw2,
                                                  const float* __restrict__ pb2,
                                                  const float* __restrict__ lw2,
                                                  float* __restrict__ x1,
                                                  float* __restrict__ cinv_out,
                                                  __half* __restrict__ y,
                                                  __half* __restrict__ aggh_zero) {
    __shared__ float s_w[64 * 64];
    __shared__ float s_x[64 * 64];
    __shared__ float s_b[64];
    __shared__ float s_ci[64];
    const int t = threadIdx.x;
    const int n0 = blockIdx.x * 64;
    const int oq = t & 15, nq = t >> 4;

    {
        float4 z = make_float4(0.f, 0.f, 0.f, 0.f);
        float4* zb = reinterpret_cast<float4*>(aggh_zero);
        int base = blockIdx.x * 512;
        for (int i = t; i < 512; i += 256) {
            int gi = base + i;
            if (gi < N_NODES * 8) zb[gi] = z;
        }
    }

    for (int idx = t; idx < 640; idx += 256)
        s_w[idx] = (idx < 320) ? lw1[idx] : rw1[idx - 320];
    if (t < 64) s_b[t] = lb1[t];
    if (t < 64) {
        int nn = min(n0 + t, N_NODES - 1);
        float c = agg8[(size_t)nn * 8 + 5];
        float ci = 1.f / fmaxf(c, 1.f);
        s_ci[t] = ci;
        if (n0 + t < N_NODES) cinv_out[n0 + t] = ci;
    }
    __syncthreads();
    for (int idx = t; idx < 640; idx += 256) {
        int i = idx >> 6, nd = idx & 63;
        int nn = min(n0 + nd, N_NODES - 1);
        s_x[i * 72 + nd] = (i < 5) ? agg8[(size_t)nn * 8 + i] * s_ci[nd]
                                   : x0p[(size_t)nn * 8 + (i - 5)];
    }
    __syncthreads();

    // ---- GEMM0: K=10 (scalar) ----
    float acc[4][4];
#pragma unroll
    for (int a = 0; a < 4; a++)
#pragma unroll
        for (int b = 0; b < 4; b++) acc[a][b] = 0.f;
#pragma unroll
    for (int i = 0; i < 10; i++) {
        float4 xv = *reinterpret_cast<const float4*>(&s_x[i * 72 + (nq << 2)]);
        float4 wv = *reinterpret_cast<const float4*>(&s_w[(i << 6) + (oq << 2)]);
        acc[0][0] += xv.x * wv.x; acc[0][1] += xv.x * wv.y; acc[0][2] += xv.x * wv.z; acc[0][3] += xv.x * wv.w;
        acc[1][0] += xv.y * wv.x; acc[1][1] += xv.y * wv.y; acc[1][2] += xv.y * wv.z; acc[1][3] += xv.y * wv.w;
        acc[2][0] += xv.z * wv.x; acc[2][1] += xv.z * wv.y; acc[2][2] += xv.z * wv.z; acc[2][3] += xv.z * wv.w;
        acc[3][0] += xv.w * wv.x; acc[3][1] += xv.w * wv.y; acc[3][2] += xv.w * wv.z; acc[3][3] += xv.w * wv.w;
    }
    float lb0 = s_b[(oq << 2) + 0], lb1v = s_b[(oq << 2) + 1];
    float lb2 = s_b[(oq << 2) + 2], lb3 = s_b[(oq << 2) + 3];
#pragma unroll
    for (int dn = 0; dn < 4; dn++) {
        float v0 = acc[dn][0] + lb0;
        float v1 = acc[dn][1] + lb1v;
        float v2 = acc[dn][2] + lb2;
        float v3 = acc[dn][3] + lb3;
        float ss = v0 * v0 + v1 * v1 + v2 * v2 + v3 * v3;
        ss += __shfl_down_sync(0xffffffffu, ss, 8, 16);
        ss += __shfl_down_sync(0xffffffffu, ss, 4, 16);
        ss += __shfl_down_sync(0xffffffffu, ss, 2, 16);
        ss += __shfl_down_sync(0xffffffffu, ss, 1, 16);
        ss = __shfl_sync(0xffffffffu, ss, 0, 16);
        float sc = 1.f / fmaxf(sqrtf(ss), EPS_NORM);
        acc[dn][0] = fmaxf(v0 * sc, 0.f);
        acc[dn][1] = fmaxf(v1 * sc, 0.f);
        acc[dn][2] = fmaxf(v2 * sc, 0.f);
        acc[dn][3] = fmaxf(v3 * sc, 0.f);
    }
    __syncthreads();

#pragma unroll
    for (int dn = 0; dn < 4; dn++) {
        int n = n0 + (nq << 2) + dn;
        if (n < N_NODES) {
            *reinterpret_cast<float4*>(&x1[(size_t)n * 64 + (oq << 2)]) =
                make_float4(acc[dn][0], acc[dn][1], acc[dn][2], acc[dn][3]);
        }
#pragma unroll
        for (int dk = 0; dk < 4; dk++)
            s_x[swidx((oq << 2) + dk, nq, dn)] = acc[dn][dk];
    }
    for (int i4 = t; i4 < 1024; i4 += 256)
        reinterpret_cast<float4*>(s_w)[i4] = reinterpret_cast<const float4*>(pw2)[i4];
    if (t < 64) s_b[t] = pb2[t];
    __syncthreads();

    // ---- GEMM1: K=64 (f32x2, hoisted) ----
    gemm64_fx2(s_x, s_w, oq, nq, acc);
    __syncthreads();
#pragma unroll
    for (int dk = 0; dk < 4; dk++) {
        float b = s_b[(oq << 2) + dk];
#pragma unroll
        for (int dn = 0; dn < 4; dn++)
            s_x[swidx((oq << 2) + dk, nq, dn)] = fmaxf(acc[dn][dk] + b, 0.f);
    }
    for (int i4 = t; i4 < 1024; i4 += 256)
        reinterpret_cast<float4*>(s_w)[i4] = reinterpret_cast<const float4*>(lw2)[i4];
    __syncthreads();

    // ---- GEMM2: K=64 (f32x2, hoisted) -> y fp16 ----
    gemm64_fx2(s_x, s_w, oq, nq, acc);
#pragma unroll
    for (int dn = 0; dn < 4; dn++) {
        int n = n0 + (nq << 2) + dn;
        if (n < N_NODES) {
            __half2 h0 = __floats2half2_rn(acc[dn][0], acc[dn][1]);
            __half2 h1 = __floats2half2_rn(acc[dn][2], acc[dn][3]);
            uint2 pack;
            pack.x = *reinterpret_cast<uint32_t*>(&h0);
            pack.y = *reinterpret_cast<uint32_t*>(&h1);
            *reinterpret_cast<uint2*>(y + (size_t)n * 64 + (oq << 2)) = pack;
        }
    }
}

// ==================== fp2: conv2 finalize + conv3 projection ====================
__global__ __launch_bounds__(256) void fp2_kernel(const float* __restrict__ x1,
                                                  const __half* __restrict__ agg,
                                                  const float* __restrict__ cinv,
                                                  const float* __restrict__ rw2,
                                                  const float* __restrict__ lb2,
                                                  const float* __restrict__ pw3,
                                                  const float* __restrict__ pb3,
                                                  const float* __restrict__ lw3,
                                                  float* __restrict__ x2,
                                                  __half* __restrict__ y8,
                                                  float* __restrict__ agg8z) {
    __shared__ float s_w[64 * 64];
    __shared__ float s_x[64 * 64];
    __shared__ float s_b[64];
    const int t = threadIdx.x;
    const int n0 = blockIdx.x * 64;
    const int oq = t & 15, nq = t >> 4;

    if (t < 128) {
        int gi = blockIdx.x * 128 + t;
        if (gi < N_NODES * 2) {
            float4 z = make_float4(0.f, 0.f, 0.f, 0.f);
            reinterpret_cast<float4*>(agg8z)[gi] = z;
        }
    }

    for (int i4 = t; i4 < 1024; i4 += 256)
        reinterpret_cast<float4*>(s_w)[i4] = reinterpret_cast<const float4*>(rw2)[i4];
    if (t < 64) s_b[t] = lb2[t];
    for (int idx = t; idx < 64 * 64; idx += 256) {
        int n = idx >> 6, i = idx & 63;
        int nn = min(n0 + n, N_NODES - 1);
        s_x[swidx(i, n >> 2, n & 3)] = x1[(size_t)nn * 64 + i];
    }
    __syncthreads();

    // ---- GEMM0: root term (f32x2, hoisted) ----
    float acc[4][4];
    gemm64_fx2(s_x, s_w, oq, nq, acc);

    float lb0 = s_b[(oq << 2) + 0], lb1v = s_b[(oq << 2) + 1];
    float lb2v = s_b[(oq << 2) + 2], lb3 = s_b[(oq << 2) + 3];
#pragma unroll
    for (int dn = 0; dn < 4; dn++) {
        int n = n0 + (nq << 2) + dn;
        int nn = min(n, N_NODES - 1);
        float ci = cinv[nn];
        uint2 raw = *reinterpret_cast<const uint2*>(agg + (size_t)nn * 64 + (oq << 2));
        float2 g0 = __half22float2(*reinterpret_cast<__half2*>(&raw.x));
        float2 g1 = __half22float2(*reinterpret_cast<__half2*>(&raw.y));
        float v0 = acc[dn][0] + lb0 + g0.x * ci;
        float v1 = acc[dn][1] + lb1v + g0.y * ci;
        float v2 = acc[dn][2] + lb2v + g1.x * ci;
        float v3 = acc[dn][3] + lb3 + g1.y * ci;
        float ss = v0 * v0 + v1 * v1 + v2 * v2 + v3 * v3;
        ss += __shfl_down_sync(0xffffffffu, ss, 8, 16);
        ss += __shfl_down_sync(0xffffffffu, ss, 4, 16);
        ss += __shfl_down_sync(0xffffffffu, ss, 2, 16);
        ss += __shfl_down_sync(0xffffffffu, ss, 1, 16);
        ss = __shfl_sync(0xffffffffu, ss, 0, 16);
        float sc = 1.f / fmaxf(sqrtf(ss), EPS_NORM);
        acc[dn][0] = fmaxf(v0 * sc, 0.f);
        acc[dn][1] = fmaxf(v1 * sc, 0.f);
        acc[dn][2] = fmaxf(v2 * sc, 0.f);
        acc[dn][3] = fmaxf(v3 * sc, 0.f);
    }
    __syncthreads();

#pragma unroll
    for (int dn = 0; dn < 4; dn++) {
        int n = n0 + (nq << 2) + dn;
        if (n < N_NODES) {
            *reinterpret_cast<float4*>(&x2[(size_t)n * 64 + (oq << 2)]) =
                make_float4(acc[dn][0], acc[dn][1], acc[dn][2], acc[dn][3]);
        }
#pragma unroll
        for (int dk = 0; dk < 4; dk++)
            s_x[swidx((oq << 2) + dk, nq, dn)] = acc[dn][dk];
    }
    for (int i4 = t; i4 < 1024; i4 += 256)
        reinterpret_cast<float4*>(s_w)[i4] = reinterpret_cast<const float4*>(pw3)[i4];
    if (t < 64) s_b[t] = pb3[t];
    __syncthreads();

    // ---- GEMM1: xp = relu(x2 @ pw3 + pb3) (f32x2, hoisted) ----
    gemm64_fx2(s_x, s_w, oq, nq, acc);
    __syncthreads();
#pragma unroll
    for (int dk = 0; dk < 4; dk++) {
        float b = s_b[(oq << 2) + dk];
#pragma unroll
        for (int dn = 0; dn < 4; dn++)
            s_x[swidx((oq << 2) + dk, nq, dn)] = fmaxf(acc[dn][dk] + b, 0.f);
    }
    for (int idx = t; idx < 64 * 8; idx += 256) s_w[idx] = 0.f;
    __syncthreads();
    for (int idx = t; idx < 64 * 5; idx += 256) s_w[(idx / 5) * 8 + (idx % 5)] = lw3[idx];
    __syncthreads();

    // ---- GEMM2: y8 = xp @ lw3 (OUTP=8, scalar, hoisted swizzle) ----
    if (oq < 2) {
        float a2[4][4];
#pragma unroll
        for (int a = 0; a < 4; a++)
#pragma unroll
            for (int b = 0; b < 4; b++) a2[a][b] = 0.f;
#pragma unroll
        for (int i4 = 0; i4 < 16; i4++) {
            const float* xb = &s_x[(i4 << 8) + (((nq ^ i4) & 15) << 2)];
            const float* wb = &s_w[(i4 << 5) + (oq << 2)];
#pragma unroll
            for (int j = 0; j < 4; j++) {
                float4 xv = *reinterpret_cast<const float4*>(xb + (j << 6));
                float4 wv = *reinterpret_cast<const float4*>(wb + (j << 3));
                a2[0][0] += xv.x * wv.x; a2[0][1] += xv.x * wv.y; a2[0][2] += xv.x * wv.z; a2[0][3] += xv.x * wv.w;
                a2[1][0] += xv.y * wv.x; a2[1][1] += xv.y * wv.y; a2[1][2] += xv.y * wv.z; a2[1][3] += xv.y * wv.w;
                a2[2][0] += xv.z * wv.x; a2[2][1] += xv.z * wv.y; a2[2][2] += xv.z * wv.z; a2[2][3] += xv.z * wv.w;
                a2[3][0] += xv.w * wv.x; a2[3][1] += xv.w * wv.y; a2[3][2] += xv.w * wv.z; a2[3][3] += xv.w * wv.w;
            }
        }
#pragma unroll
        for (int dn = 0; dn < 4; dn++) {
            int n = n0 + (nq << 2) + dn;
            if (n < N_NODES) {
                __half2 h0 = __floats2half2_rn(a2[dn][0], a2[dn][1]);
                __half2 h1 = __floats2half2_rn(a2[dn][2], a2[dn][3]);
                uint2 pack;
                pack.x = *reinterpret_cast<uint32_t*>(&h0);
                pack.y = *reinterpret_cast<uint32_t*>(&h1);
                *reinterpret_cast<uint2*>(y8 + (size_t)n * 8 + (oq << 2)) = pack;
            }
        }
    }
}

// ------- conv3 finalize: out5 = agg*cinv + lb + x2@rw ; norm (no relu) -------
__global__ __launch_bounds__(128) void fin3_kernel(const float* __restrict__ x2,
                                                   const float* __restrict__ agg8,
                                                   const float* __restrict__ cinv,
                                                   const float* __restrict__ rw,
                                                   const float* __restrict__ lb,
                                                   float* __restrict__ out) {
    __shared__ float s_rw[64 * 8];
    __shared__ float s_lb[8];
    int t = threadIdx.x;
    for (int idx = t; idx < 320; idx += 128) s_rw[(idx / 5) * 8 + (idx % 5)] = rw[idx];
    if (t < 5) s_lb[t] = lb[t];
    __syncthreads();
    int n = blockIdx.x * 128 + t;
    if (n >= N_NODES) return;

    float ci = cinv[n];
    const float4* av = reinterpret_cast<const float4*>(agg8 + (size_t)n * 8);
    float4 a0 = av[0], a1 = av[1];
    float4 vf = make_float4(s_lb[0] + a0.x * ci, s_lb[1] + a0.y * ci,
                            s_lb[2] + a0.z * ci, s_lb[3] + a0.w * ci);
    float v4 = s_lb[4] + a1.x * ci;

    const float4* xr = reinterpret_cast<const float4*>(x2 + (size_t)n * 64);
#pragma unroll
    for (int iq = 0; iq < 16; iq++) {
        float4 xv = xr[iq];
        float xs[4] = {xv.x, xv.y, xv.z, xv.w};
#pragma unroll
        for (int c = 0; c < 4; c++) {
            int i = iq * 4 + c;
            float4 w = *reinterpret_cast<const float4*>(&s_rw[i * 8]);
            float w4 = s_rw[i * 8 + 4];
            vf.x += xs[c] * w.x;
            vf.y += xs[c] * w.y;
            vf.z += xs[c] * w.z;
            vf.w += xs[c] * w.w;
            v4 += xs[c] * w4;
        }
    }
    float ss = vf.x * vf.x + vf.y * vf.y + vf.z * vf.z + vf.w * vf.w + v4 * v4;
    float sc = 1.f / fmaxf(sqrtf(ss), EPS_NORM);
    float* o = out + (size_t)n * 5;
    o[0] = vf.x * sc;
    o[1] = vf.y * sc;
    o[2] = vf.z * sc;
    o[3] = vf.w * sc;
    o[4] = v4 * sc;
}

// ---------------- host launcher ----------------
extern "C" void kernel_launch(void* const* d_in, const int* in_sizes, int n_in,
                              void* d_out, int out_size) {
    const float* h = (const float*)d_in[0];
    const int* ei = (const int*)d_in[1];
    const float* ew = (const float*)d_in[2];
    const float* gamma = (const float*)d_in[3];
    const float* beta = (const float*)d_in[4];
    const float* c1_pw = (const float*)d_in[5];
    const float* c1_pb = (const float*)d_in[6];
    const float* c1_lw = (const float*)d_in[7];
    const float* c1_lb = (const float*)d_in[8];
    const float* c1_rw = (const float*)d_in[9];
    const float* c2_pw = (const float*)d_in[10];
    const float* c2_pb = (const float*)d_in[11];
    const float* c2_lw = (const float*)d_in[12];
    const float* c2_lb = (const float*)d_in[13];
    const float* c2_rw = (const float*)d_in[14];
    const float* c3_pw = (const float*)d_in[15];
    const float* c3_pb = (const float*)d_in[16];
    const float* c3_lw = (const float*)d_in[17];
    const float* c3_lb = (const float*)d_in[18];
    const float* c3_rw = (const float*)d_in[19];
    float* out = (float*)d_out;

    const int* src = ei;
    const int* dst = ei + N_EDGES;

    float *x0, *x1, *x2, *agg8, *cinv, *part;
    __half *yh, *aggh;
    cudaGetSymbolAddress((void**)&x0, g_x0);
    cudaGetSymbolAddress((void**)&x1, g_x1);
    cudaGetSymbolAddress((void**)&x2, g_x2);
    cudaGetSymbolAddress((void**)&yh, g_yh);
    cudaGetSymbolAddress((void**)&aggh, g_aggh);
    cudaGetSymbolAddress((void**)&agg8, g_agg8);
    cudaGetSymbolAddress((void**)&cinv, g_cinv);
    cudaGetSymbolAddress((void**)&part, g_part);

    const int NB64 = (N_NODES + 63) / 64;   // 1563

    // 1: BN partial stats
    bn_stats_kernel<<<148, 256>>>(h, part);
    // 2: BN apply + conv1 5x5 projection; zeroes agg8
    bn_conv1_kernel<<<(N_NODES + 255) / 256, 256>>>(h, part, gamma, beta, c1_pw, c1_pb,
                                                    x0, yh, agg8);
    // 3: conv1 push-scatter (width 5 + cnt)
    scatter8_kernel<true><<<6250, 256>>>(src, dst, ew, yh, agg8);
    // 4: FUSED conv1-finalize + conv2-projection
    fp1_kernel<<<NB64, 256>>>(x0, agg8, c1_lw, c1_lb, c1_rw,
                              c2_pw, c2_pb, c2_lw, x1, cinv, yh, aggh);
    // 5: conv2 push-scatter (v4.f16x2 atomics, 8 lanes/edge)
    scatter64_kernel<<<4096, 256>>>(src, dst, ew, yh, aggh);
    // 6: FUSED conv2-finalize + conv3-projection (zeroes agg8)
    fp2_kernel<<<NB64, 256>>>(x1, aggh, cinv, c2_rw, c2_lb,
                              c3_pw, c3_pb, c3_lw, x2, yh, agg8);
    // 7: conv3 push-scatter (width 5)
    scatter8_kernel<false><<<6250, 256>>>(src, dst, ew, yh, agg8);
    // 8: conv3 finalize
    fin3_kernel<<<(N_NODES + 127) / 128, 128>>>(x2, agg8, cinv, c3_rw, c3_lb, out);
}

// round 15
// speedup vs baseline: 1.0518x; 1.0125x over previous
#include <cuda_runtime.h>
#include <cuda_fp16.h>
#include <cstdint>
#include <math.h>

#define N_NODES 100000
#define N_EDGES 3200000
#define EPS_BN 1e-5f
#define EPS_NORM 1e-12f

// ---------------- device scratch (no allocation allowed) ----------------
__device__ __align__(16) float g_x0[N_NODES * 8];
__device__ __align__(16) float g_x1[N_NODES * 64];
__device__ __align__(16) float g_x2[N_NODES * 64];
__device__ __align__(16) __half g_yh[N_NODES * 64];
__device__ __align__(16) __half g_aggh[N_NODES * 64];
__device__ __align__(32) float g_agg8[N_NODES * 8];
__device__ float g_cinv[N_NODES];
__device__ __align__(16) float g_part[148 * 16];

// ---------------- vector reductions ----------------
__device__ __forceinline__ void red_add_v4(float* p, float4 v) {
    asm volatile("red.global.add.v4.f32 [%0], {%1,%2,%3,%4};"
                 :: "l"(p), "f"(v.x), "f"(v.y), "f"(v.z), "f"(v.w) : "memory");
}
__device__ __forceinline__ void red_add_v2(float* p, float a, float b) {
    asm volatile("red.global.add.v2.f32 [%0], {%1,%2};"
                 :: "l"(p), "f"(a), "f"(b) : "memory");
}
__device__ __forceinline__ void red_add_f32(float* p, float a) {
    asm volatile("red.global.add.f32 [%0], %1;"
                 :: "l"(p), "f"(a) : "memory");
}
__device__ __forceinline__ void red_add_v4_h2(__half* p, uint32_t a, uint32_t b,
                                              uint32_t c, uint32_t d) {
    asm volatile("red.global.add.noftz.v4.f16x2 [%0], {%1,%2,%3,%4};"
                 :: "l"(p), "r"(a), "r"(b), "r"(c), "r"(d) : "memory");
}

// ---------------- packed f32x2 FMA helpers ----------------
__device__ __forceinline__ unsigned long long pack2(float v) {
    unsigned long long r;
    asm("mov.b64 %0, {%1, %1};" : "=l"(r) : "f"(v));
    return r;
}
__device__ __forceinline__ unsigned long long fma2(unsigned long long a,
                                                   unsigned long long b,
                                                   unsigned long long c) {
    unsigned long long d;
    asm("fma.rn.f32x2 %0, %1, %2, %3;" : "=l"(d) : "l"(a), "l"(b), "l"(c));
    return d;
}
__device__ __forceinline__ void unpack2(unsigned long long p, float& lo, float& hi) {
    asm("mov.b64 {%0, %1}, %2;" : "=f"(lo), "=f"(hi) : "l"(p));
}

__device__ __forceinline__ int swidx(int row, int cg, int c) {
    return (row << 6) + (((cg ^ ((row >> 2) & 15)) & 15) << 2) + c;
}

// ---- K=64 GEMM via f32x2, hoisted swizzle ----
__device__ __forceinline__ void gemm64_fx2(const float* __restrict__ s_x,
                                           const float* __restrict__ s_w,
                                           int oq, int nq, float acc[4][4]) {
    unsigned long long a2[2][4];
#pragma unroll
    for (int p = 0; p < 2; p++)
#pragma unroll
        for (int k = 0; k < 4; k++) a2[p][k] = 0ull;
#pragma unroll
    for (int i4 = 0; i4 < 16; i4++) {
        const float* xb = &s_x[(i4 << 8) + (((nq ^ i4) & 15) << 2)];
        const float* wb = &s_w[(i4 << 8) + (oq << 2)];
#pragma unroll
        for (int j = 0; j < 4; j++) {
            ulonglong2 xp = *reinterpret_cast<const ulonglong2*>(xb + (j << 6));
            float4 wv = *reinterpret_cast<const float4*>(wb + (j << 6));
            unsigned long long w0 = pack2(wv.x), w1 = pack2(wv.y);
            unsigned long long w2 = pack2(wv.z), w3 = pack2(wv.w);
            a2[0][0] = fma2(xp.x, w0, a2[0][0]);
            a2[0][1] = fma2(xp.x, w1, a2[0][1]);
            a2[0][2] = fma2(xp.x, w2, a2[0][2]);
            a2[0][3] = fma2(xp.x, w3, a2[0][3]);
            a2[1][0] = fma2(xp.y, w0, a2[1][0]);
            a2[1][1] = fma2(xp.y, w1, a2[1][1]);
            a2[1][2] = fma2(xp.y, w2, a2[1][2]);
            a2[1][3] = fma2(xp.y, w3, a2[1][3]);
        }
    }
#pragma unroll
    for (int k = 0; k < 4; k++) {
        unpack2(a2[0][k], acc[0][k], acc[1][k]);
        unpack2(a2[1][k], acc[2][k], acc[3][k]);
    }
}

// ------- BatchNorm statistics -------
__global__ __launch_bounds__(256) void bn_stats_kernel(const float* __restrict__ h,
                                                       float* __restrict__ part) {
    float s[5] = {0, 0, 0, 0, 0}, q[5] = {0, 0, 0, 0, 0};
    int stride = gridDim.x * blockDim.x;
    for (int n = blockIdx.x * blockDim.x + threadIdx.x; n < N_NODES; n += stride) {
#pragma unroll
        for (int i = 0; i < 5; i++) {
            float v = h[n * 5 + i];
            s[i] += v;
            q[i] += v * v;
        }
    }
#pragma unroll
    for (int k = 16; k > 0; k >>= 1) {
#pragma unroll
        for (int i = 0; i < 5; i++) {
            s[i] += __shfl_down_sync(0xffffffffu, s[i], k);
            q[i] += __shfl_down_sync(0xffffffffu, q[i], k);
        }
    }
    __shared__ float sh[10];
    if (threadIdx.x < 10) sh[threadIdx.x] = 0.f;
    __syncthreads();
    if ((threadIdx.x & 31) == 0) {
#pragma unroll
        for (int i = 0; i < 5; i++) {
            atomicAdd(&sh[i], s[i]);
            atomicAdd(&sh[5 + i], q[i]);
        }
    }
    __syncthreads();
    if (threadIdx.x < 10) part[blockIdx.x * 16 + threadIdx.x] = sh[threadIdx.x];
}

// ------- BN apply + conv1 projection -> fp16 y8 ; zero agg8 -------
__global__ __launch_bounds__(256) void bn_conv1_kernel(const float* __restrict__ h,
                                                       const float* __restrict__ part,
                                                       const float* __restrict__ gamma,
                                                       const float* __restrict__ beta,
                                                       const float* __restrict__ pw,
                                                       const float* __restrict__ pb,
                                                       float* __restrict__ x0p,
                                                       __half* __restrict__ y8,
                                                       float* __restrict__ agg8) {
    __shared__ float s_warp[8][10];
    __shared__ float s_stats[10];
    int t = threadIdx.x;
    int lane = t & 31, wid = t >> 5;
    {
        float v[10];
#pragma unroll
        for (int i = 0; i < 10; i++) v[i] = 0.f;
        if (t < 148) {
#pragma unroll
            for (int i = 0; i < 10; i++) v[i] = part[t * 16 + i];
        }
#pragma unroll
        for (int k = 16; k > 0; k >>= 1) {
#pragma unroll
            for (int i = 0; i < 10; i++) v[i] += __shfl_down_sync(0xffffffffu, v[i], k);
        }
        if (lane == 0) {
#pragma unroll
            for (int i = 0; i < 10; i++) s_warp[wid][i] = v[i];
        }
    }
    __syncthreads();
    if (t < 10) {
        float acc = 0.f;
#pragma unroll
        for (int w = 0; w < 8; w++) acc += s_warp[w][t];
        s_stats[t] = acc;
    }
    __syncthreads();

    int n = blockIdx.x * blockDim.x + t;
    if (n >= N_NODES) return;
    const float inv_n = 1.f / (float)N_NODES;
    float xr[5];
#pragma unroll
    for (int i = 0; i < 5; i++) {
        float mu = s_stats[i] * inv_n;
        float var = s_stats[5 + i] * inv_n - mu * mu;
        float sc = rsqrtf(var + EPS_BN) * gamma[i];
        xr[i] = (h[n * 5 + i] - mu) * sc + beta[i];
    }
    float4* x0v = reinterpret_cast<float4*>(x0p + (size_t)n * 8);
    x0v[0] = make_float4(xr[0], xr[1], xr[2], xr[3]);
    x0v[1] = make_float4(xr[4], 0.f, 0.f, 0.f);
    float xp[5];
#pragma unroll
    for (int k = 0; k < 5; k++) {
        float v = pb[k];
#pragma unroll
        for (int i = 0; i < 5; i++) v += xr[i] * pw[i * 5 + k];
        xp[k] = fmaxf(v, 0.f);
    }
    __half2 h0 = __floats2half2_rn(xp[0], xp[1]);
    __half2 h1 = __floats2half2_rn(xp[2], xp[3]);
    __half2 h2 = __floats2half2_rn(xp[4], 0.f);
    uint4 pack;
    pack.x = *reinterpret_cast<uint32_t*>(&h0);
    pack.y = *reinterpret_cast<uint32_t*>(&h1);
    pack.z = *reinterpret_cast<uint32_t*>(&h2);
    pack.w = 0u;
    *reinterpret_cast<uint4*>(y8 + (size_t)n * 8) = pack;
    float4* av = reinterpret_cast<float4*>(agg8 + (size_t)n * 8);
    float4 z = make_float4(0.f, 0.f, 0.f, 0.f);
    av[0] = z;
    av[1] = z;
}

// -------- width-8 push scatter (one edge per thread) --------
template <bool ADD_CNT>
__global__ void scatter8_kernel(const int* __restrict__ src,
                                const int* __restrict__ dst,
                                const float* __restrict__ ew,
                                const __half* __restrict__ y8,
                                float* __restrict__ agg8) {
    int stride = gridDim.x * blockDim.x;
    for (int e = blockIdx.x * blockDim.x + threadIdx.x; e < N_EDGES; e += stride) {
        int s = __ldg(&src[e]);
        int d = __ldg(&dst[e]);
        float w = __ldg(&ew[e]);
        uint4 raw = *reinterpret_cast<const uint4*>(y8 + (size_t)s * 8);
        float2 f0 = __half22float2(*reinterpret_cast<__half2*>(&raw.x));
        float2 f1 = __half22float2(*reinterpret_cast<__half2*>(&raw.y));
        float2 f2 = __half22float2(*reinterpret_cast<__half2*>(&raw.z));
        red_add_v4(agg8 + (size_t)d * 8,
                   make_float4(f0.x * w, f0.y * w, f1.x * w, f1.y * w));
        if (ADD_CNT)
            red_add_v2(agg8 + (size_t)d * 8 + 4, f2.x * w, 1.0f);
        else
            red_add_f32(agg8 + (size_t)d * 8 + 4, f2.x * w);
    }
}

// -------- width-64 push scatter: 8 lanes/edge, v4.f16x2 atomics --------
__global__ void scatter64_kernel(const int* __restrict__ src,
                                 const int* __restrict__ dst,
                                 const float* __restrict__ ew,
                                 const __half* __restrict__ y,
                                 __half* __restrict__ agg) {
    int lane = threadIdx.x & 31;
    int warp = (blockIdx.x * blockDim.x + threadIdx.x) >> 5;
    int nwarps = (gridDim.x * blockDim.x) >> 5;
    int quarter = lane >> 3;
    int fo = (lane & 7) << 3;
    const int ngroups = N_EDGES / 4;
    for (int p = warp; p < ngroups; p += nwarps) {
        int e = 4 * p + quarter;
        int s = __ldg(&src[e]);
        int d = __ldg(&dst[e]);
        float w = __ldg(&ew[e]);
        uint4 raw = *reinterpret_cast<const uint4*>(y + (size_t)s * 64 + fo);
        float2 f0 = __half22float2(*reinterpret_cast<__half2*>(&raw.x));
        float2 f1 = __half22float2(*reinterpret_cast<__half2*>(&raw.y));
        float2 f2 = __half22float2(*reinterpret_cast<__half2*>(&raw.z));
        float2 f3 = __half22float2(*reinterpret_cast<__half2*>(&raw.w));
        __half2 h0 = __floats2half2_rn(f0.x * w, f0.y * w);
        __half2 h1 = __floats2half2_rn(f1.x * w, f1.y * w);
        __half2 h2 = __floats2half2_rn(f2.x * w, f2.y * w);
        __half2 h3 = __floats2half2_rn(f3.x * w, f3.y * w);
        red_add_v4_h2(agg + (size_t)d * 64 + fo,
                      *reinterpret_cast<uint32_t*>(&h0),
                      *reinterpret_cast<uint32_t*>(&h1),
                      *reinterpret_cast<uint32_t*>(&h2),
                      *reinterpret_cast<uint32_t*>(&h3));
    }
}

// ==================== fp1: conv1 finalize + conv2 projection (PDL) ====================
__global__ __launch_bounds__(256) void fp1_kernel(const float* __restrict__ x0p,
                                                  const float* __restrict__ agg8,
                                                  const float* __restrict__ lw1,
                                                  const float* __restrict__ lb1,
                                                  const float* __restrict__ rw1,
                                                  const float* __restrict__ pw2,
                                                  const float* __restrict__ pb2,
                                                  const float* __restrict__ lw2,
                                                  float* __restrict__ x1,
                                                  float* __restrict__ cinv_out,
                                                  __half* __restrict__ y,
                                                  __half* __restrict__ aggh_zero) {
    __shared__ float s_w[64 * 64];
    __shared__ float s_x[64 * 64];
    __shared__ float s_b[64];
    __shared__ float s_ci[64];
    const int t = threadIdx.x;
    const int n0 = blockIdx.x * 64;
    const int oq = t & 15, nq = t >> 4;

    // ------- PDL prologue (independent of scatter8<true>) -------
    {
        float4 z = make_float4(0.f, 0.f, 0.f, 0.f);
        float4* zb = reinterpret_cast<float4*>(aggh_zero);
        int base = blockIdx.x * 512;
        for (int i = t; i < 512; i += 256) {
            int gi = base + i;
            if (gi < N_NODES * 8) zb[gi] = z;
        }
    }
    for (int idx = t; idx < 640; idx += 256)
        s_w[idx] = (idx < 320) ? lw1[idx] : rw1[idx - 320];
    if (t < 64) s_b[t] = lb1[t];

#if __CUDA_ARCH__ >= 900
    cudaGridDependencySynchronize();
#endif

    if (t < 64) {
        int nn = min(n0 + t, N_NODES - 1);
        float c = agg8[(size_t)nn * 8 + 5];
        float ci = 1.f / fmaxf(c, 1.f);
        s_ci[t] = ci;
        if (n0 + t < N_NODES) cinv_out[n0 + t] = ci;
    }
    __syncthreads();
    for (int idx = t; idx < 640; idx += 256) {
        int i = idx >> 6, nd = idx & 63;
        int nn = min(n0 + nd, N_NODES - 1);
        s_x[i * 72 + nd] = (i < 5) ? agg8[(size_t)nn * 8 + i] * s_ci[nd]
                                   : x0p[(size_t)nn * 8 + (i - 5)];
    }
    __syncthreads();

    // ---- GEMM0: K=10 ----
    float acc[4][4];
#pragma unroll
    for (int a = 0; a < 4; a++)
#pragma unroll
        for (int b = 0; b < 4; b++) acc[a][b] = 0.f;
#pragma unroll
    for (int i = 0; i < 10; i++) {
        float4 xv = *reinterpret_cast<const float4*>(&s_x[i * 72 + (nq << 2)]);
        float4 wv = *reinterpret_cast<const float4*>(&s_w[(i << 6) + (oq << 2)]);
        acc[0][0] += xv.x * wv.x; acc[0][1] += xv.x * wv.y; acc[0][2] += xv.x * wv.z; acc[0][3] += xv.x * wv.w;
        acc[1][0] += xv.y * wv.x; acc[1][1] += xv.y * wv.y; acc[1][2] += xv.y * wv.z; acc[1][3] += xv.y * wv.w;
        acc[2][0] += xv.z * wv.x; acc[2][1] += xv.z * wv.y; acc[2][2] += xv.z * wv.z; acc[2][3] += xv.z * wv.w;
        acc[3][0] += xv.w * wv.x; acc[3][1] += xv.w * wv.y; acc[3][2] += xv.w * wv.z; acc[3][3] += xv.w * wv.w;
    }
    float lb0 = s_b[(oq << 2) + 0], lb1v = s_b[(oq << 2) + 1];
    float lb2 = s_b[(oq << 2) + 2], lb3 = s_b[(oq << 2) + 3];
#pragma unroll
    for (int dn = 0; dn < 4; dn++) {
        float v0 = acc[dn][0] + lb0;
        float v1 = acc[dn][1] + lb1v;
        float v2 = acc[dn][2] + lb2;
        float v3 = acc[dn][3] + lb3;
        float ss = v0 * v0 + v1 * v1 + v2 * v2 + v3 * v3;
        ss += __shfl_down_sync(0xffffffffu, ss, 8, 16);
        ss += __shfl_down_sync(0xffffffffu, ss, 4, 16);
        ss += __shfl_down_sync(0xffffffffu, ss, 2, 16);
        ss += __shfl_down_sync(0xffffffffu, ss, 1, 16);
        ss = __shfl_sync(0xffffffffu, ss, 0, 16);
        float sc = 1.f / fmaxf(sqrtf(ss), EPS_NORM);
        acc[dn][0] = fmaxf(v0 * sc, 0.f);
        acc[dn][1] = fmaxf(v1 * sc, 0.f);
        acc[dn][2] = fmaxf(v2 * sc, 0.f);
        acc[dn][3] = fmaxf(v3 * sc, 0.f);
    }
    __syncthreads();

#pragma unroll
    for (int dn = 0; dn < 4; dn++) {
        int n = n0 + (nq << 2) + dn;
        if (n < N_NODES) {
            *reinterpret_cast<float4*>(&x1[(size_t)n * 64 + (oq << 2)]) =
                make_float4(acc[dn][0], acc[dn][1], acc[dn][2], acc[dn][3]);
        }
#pragma unroll
        for (int dk = 0; dk < 4; dk++)
            s_x[swidx((oq << 2) + dk, nq, dn)] = acc[dn][dk];
    }
    for (int i4 = t; i4 < 1024; i4 += 256)
        reinterpret_cast<float4*>(s_w)[i4] = reinterpret_cast<const float4*>(pw2)[i4];
    if (t < 64) s_b[t] = pb2[t];
    __syncthreads();

    // ---- GEMM1 ----
    gemm64_fx2(s_x, s_w, oq, nq, acc);
    __syncthreads();
#pragma unroll
    for (int dk = 0; dk < 4; dk++) {
        float b = s_b[(oq << 2) + dk];
#pragma unroll
        for (int dn = 0; dn < 4; dn++)
            s_x[swidx((oq << 2) + dk, nq, dn)] = fmaxf(acc[dn][dk] + b, 0.f);
    }
    for (int i4 = t; i4 < 1024; i4 += 256)
        reinterpret_cast<float4*>(s_w)[i4] = reinterpret_cast<const float4*>(lw2)[i4];
    __syncthreads();

    // ---- GEMM2 -> y fp16 ----
    gemm64_fx2(s_x, s_w, oq, nq, acc);
#pragma unroll
    for (int dn = 0; dn < 4; dn++) {
        int n = n0 + (nq << 2) + dn;
        if (n < N_NODES) {
            __half2 h0 = __floats2half2_rn(acc[dn][0], acc[dn][1]);
            __half2 h1 = __floats2half2_rn(acc[dn][2], acc[dn][3]);
            uint2 pack;
            pack.x = *reinterpret_cast<uint32_t*>(&h0);
            pack.y = *reinterpret_cast<uint32_t*>(&h1);
            *reinterpret_cast<uint2*>(y + (size_t)n * 64 + (oq << 2)) = pack;
        }
    }
}

// ==================== fp2: conv2 finalize + conv3 projection (PDL) ====================
__global__ __launch_bounds__(256) void fp2_kernel(const float* __restrict__ x1,
                                                  const __half* __restrict__ agg,
                                                  const float* __restrict__ cinv,
                                                  const float* __restrict__ rw2,
                                                  const float* __restrict__ lb2,
                                                  const float* __restrict__ pw3,
                                                  const float* __restrict__ pb3,
                                                  const float* __restrict__ lw3,
                                                  float* __restrict__ x2,
                                                  __half* __restrict__ y8,
                                                  float* __restrict__ agg8z) {
    __shared__ float s_w[64 * 64];
    __shared__ float s_x[64 * 64];
    __shared__ float s_b[64];
    const int t = threadIdx.x;
    const int n0 = blockIdx.x * 64;
    const int oq = t & 15, nq = t >> 4;

    // ------- PDL prologue: everything up to and including GEMM0 is
    // independent of scatter64 (depends only on fp1 outputs + weights) -------
    if (t < 128) {
        int gi = blockIdx.x * 128 + t;
        if (gi < N_NODES * 2) {
            float4 z = make_float4(0.f, 0.f, 0.f, 0.f);
            reinterpret_cast<float4*>(agg8z)[gi] = z;
        }
    }
    for (int i4 = t; i4 < 1024; i4 += 256)
        reinterpret_cast<float4*>(s_w)[i4] = reinterpret_cast<const float4*>(rw2)[i4];
    if (t < 64) s_b[t] = lb2[t];
    for (int idx = t; idx < 64 * 64; idx += 256) {
        int n = idx >> 6, i = idx & 63;
        int nn = min(n0 + n, N_NODES - 1);
        s_x[swidx(i, n >> 2, n & 3)] = x1[(size_t)nn * 64 + i];
    }
    __syncthreads();

    // ---- GEMM0: root term (scatter-independent) ----
    float acc[4][4];
    gemm64_fx2(s_x, s_w, oq, nq, acc);

#if __CUDA_ARCH__ >= 900
    cudaGridDependencySynchronize();   // wait for scatter64's aggh
#endif

    float lb0 = s_b[(oq << 2) + 0], lb1v = s_b[(oq << 2) + 1];
    float lb2v = s_b[(oq << 2) + 2], lb3 = s_b[(oq << 2) + 3];
#pragma unroll
    for (int dn = 0; dn < 4; dn++) {
        int n = n0 + (nq << 2) + dn;
        int nn = min(n, N_NODES - 1);
        float ci = cinv[nn];
        uint2 raw = *reinterpret_cast<const uint2*>(agg + (size_t)nn * 64 + (oq << 2));
        float2 g0 = __half22float2(*reinterpret_cast<__half2*>(&raw.x));
        float2 g1 = __half22float2(*reinterpret_cast<__half2*>(&raw.y));
        float v0 = acc[dn][0] + lb0 + g0.x * ci;
        float v1 = acc[dn][1] + lb1v + g0.y * ci;
        float v2 = acc[dn][2] + lb2v + g1.x * ci;
        float v3 = acc[dn][3] + lb3 + g1.y * ci;
        float ss = v0 * v0 + v1 * v1 + v2 * v2 + v3 * v3;
        ss += __shfl_down_sync(0xffffffffu, ss, 8, 16);
        ss += __shfl_down_sync(0xffffffffu, ss, 4, 16);
        ss += __shfl_down_sync(0xffffffffu, ss, 2, 16);
        ss += __shfl_down_sync(0xffffffffu, ss, 1, 16);
        ss = __shfl_sync(0xffffffffu, ss, 0, 16);
        float sc = 1.f / fmaxf(sqrtf(ss), EPS_NORM);
        acc[dn][0] = fmaxf(v0 * sc, 0.f);
        acc[dn][1] = fmaxf(v1 * sc, 0.f);
        acc[dn][2] = fmaxf(v2 * sc, 0.f);
        acc[dn][3] = fmaxf(v3 * sc, 0.f);
    }
    __syncthreads();

#pragma unroll
    for (int dn = 0; dn < 4; dn++) {
        int n = n0 + (nq << 2) + dn;
        if (n < N_NODES) {
            *reinterpret_cast<float4*>(&x2[(size_t)n * 64 + (oq << 2)]) =
                make_float4(acc[dn][0], acc[dn][1], acc[dn][2], acc[dn][3]);
        }
#pragma unroll
        for (int dk = 0; dk < 4; dk++)
            s_x[swidx((oq << 2) + dk, nq, dn)] = acc[dn][dk];
    }
    for (int i4 = t; i4 < 1024; i4 += 256)
        reinterpret_cast<float4*>(s_w)[i4] = reinterpret_cast<const float4*>(pw3)[i4];
    if (t < 64) s_b[t] = pb3[t];
    __syncthreads();

    // ---- GEMM1 ----
    gemm64_fx2(s_x, s_w, oq, nq, acc);
    __syncthreads();
#pragma unroll
    for (int dk = 0; dk < 4; dk++) {
        float b = s_b[(oq << 2) + dk];
#pragma unroll
        for (int dn = 0; dn < 4; dn++)
            s_x[swidx((oq << 2) + dk, nq, dn)] = fmaxf(acc[dn][dk] + b, 0.f);
    }
    for (int idx = t; idx < 64 * 8; idx += 256) s_w[idx] = 0.f;
    __syncthreads();
    for (int idx = t; idx < 64 * 5; idx += 256) s_w[(idx / 5) * 8 + (idx % 5)] = lw3[idx];
    __syncthreads();

    // ---- GEMM2: y8 = xp @ lw3 ----
    if (oq < 2) {
        float a2[4][4];
#pragma unroll
        for (int a = 0; a < 4; a++)
#pragma unroll
            for (int b = 0; b < 4; b++) a2[a][b] = 0.f;
#pragma unroll
        for (int i4 = 0; i4 < 16; i4++) {
            const float* xb = &s_x[(i4 << 8) + (((nq ^ i4) & 15) << 2)];
            const float* wb = &s_w[(i4 << 5) + (oq << 2)];
#pragma unroll
            for (int j = 0; j < 4; j++) {
                float4 xv = *reinterpret_cast<const float4*>(xb + (j << 6));
                float4 wv = *reinterpret_cast<const float4*>(wb + (j << 3));
                a2[0][0] += xv.x * wv.x; a2[0][1] += xv.x * wv.y; a2[0][2] += xv.x * wv.z; a2[0][3] += xv.x * wv.w;
                a2[1][0] += xv.y * wv.x; a2[1][1] += xv.y * wv.y; a2[1][2] += xv.y * wv.z; a2[1][3] += xv.y * wv.w;
                a2[2][0] += xv.z * wv.x; a2[2][1] += xv.z * wv.y; a2[2][2] += xv.z * wv.z; a2[2][3] += xv.z * wv.w;
                a2[3][0] += xv.w * wv.x; a2[3][1] += xv.w * wv.y; a2[3][2] += xv.w * wv.z; a2[3][3] += xv.w * wv.w;
            }
        }
#pragma unroll
        for (int dn = 0; dn < 4; dn++) {
            int n = n0 + (nq << 2) + dn;
            if (n < N_NODES) {
                __half2 h0 = __floats2half2_rn(a2[dn][0], a2[dn][1]);
                __half2 h1 = __floats2half2_rn(a2[dn][2], a2[dn][3]);
                uint2 pack;
                pack.x = *reinterpret_cast<uint32_t*>(&h0);
                pack.y = *reinterpret_cast<uint32_t*>(&h1);
                *reinterpret_cast<uint2*>(y8 + (size_t)n * 8 + (oq << 2)) = pack;
            }
        }
    }
}

// ------- conv3 finalize (PDL): GEMM first, agg terms after sync -------
__global__ __launch_bounds__(128) void fin3_kernel(const float* __restrict__ x2,
                                                   const float* __restrict__ agg8,
                                                   const float* __restrict__ cinv,
                                                   const float* __restrict__ rw,
                                                   const float* __restrict__ lb,
                                                   float* __restrict__ out) {
    __shared__ float s_rw[64 * 8];
    __shared__ float s_lb[8];
    int t = threadIdx.x;
    for (int idx = t; idx < 320; idx += 128) s_rw[(idx / 5) * 8 + (idx % 5)] = rw[idx];
    if (t < 5) s_lb[t] = lb[t];
    __syncthreads();
    int n = blockIdx.x * 128 + t;
    if (n >= N_NODES) n = N_NODES - 1;  // clamp; final store guarded below

    // scatter-independent: GEMM over x2 (written by fp2)
    float4 vf = make_float4(0.f, 0.f, 0.f, 0.f);
    float v4 = 0.f;
    const float4* xr = reinterpret_cast<const float4*>(x2 + (size_t)n * 64);
#pragma unroll
    for (int iq = 0; iq < 16; iq++) {
        float4 xv = xr[iq];
        float xs[4] = {xv.x, xv.y, xv.z, xv.w};
#pragma unroll
        for (int c = 0; c < 4; c++) {
            int i = iq * 4 + c;
            float4 w = *reinterpret_cast<const float4*>(&s_rw[i * 8]);
            float w4 = s_rw[i * 8 + 4];
            vf.x += xs[c] * w.x;
            vf.y += xs[c] * w.y;
            vf.z += xs[c] * w.z;
            vf.w += xs[c] * w.w;
            v4 += xs[c] * w4;
        }
    }

#if __CUDA_ARCH__ >= 900
    cudaGridDependencySynchronize();   // wait for scatter8<false>'s agg8
#endif

    float ci = cinv[n];
    const float4* av = reinterpret_cast<const float4*>(agg8 + (size_t)n * 8);
    float4 a0 = av[0], a1 = av[1];
    vf.x += s_lb[0] + a0.x * ci;
    vf.y += s_lb[1] + a0.y * ci;
    vf.z += s_lb[2] + a0.z * ci;
    vf.w += s_lb[3] + a0.w * ci;
    v4 += s_lb[4] + a1.x * ci;

    float ss = vf.x * vf.x + vf.y * vf.y + vf.z * vf.z + vf.w * vf.w + v4 * v4;
    float sc = 1.f / fmaxf(sqrtf(ss), EPS_NORM);
    int nout = blockIdx.x * 128 + t;
    if (nout < N_NODES) {
        float* o = out + (size_t)nout * 5;
        o[0] = vf.x * sc;
        o[1] = vf.y * sc;
        o[2] = vf.z * sc;
        o[3] = vf.w * sc;
        o[4] = v4 * sc;
    }
}

// ---------------- host launcher ----------------
extern "C" void kernel_launch(void* const* d_in, const int* in_sizes, int n_in,
                              void* d_out, int out_size) {
    const float* h = (const float*)d_in[0];
    const int* ei = (const int*)d_in[1];
    const float* ew = (const float*)d_in[2];
    const float* gamma = (const float*)d_in[3];
    const float* beta = (const float*)d_in[4];
    const float* c1_pw = (const float*)d_in[5];
    const float* c1_pb = (const float*)d_in[6];
    const float* c1_lw = (const float*)d_in[7];
    const float* c1_lb = (const float*)d_in[8];
    const float* c1_rw = (const float*)d_in[9];
    const float* c2_pw = (const float*)d_in[10];
    const float* c2_pb = (const float*)d_in[11];
    const float* c2_lw = (const float*)d_in[12];
    const float* c2_lb = (const float*)d_in[13];
    const float* c2_rw = (const float*)d_in[14];
    const float* c3_pw = (const float*)d_in[15];
    const float* c3_pb = (const float*)d_in[16];
    const float* c3_lw = (const float*)d_in[17];
    const float* c3_lb = (const float*)d_in[18];
    const float* c3_rw = (const float*)d_in[19];
    float* out = (float*)d_out;

    const int* src = ei;
    const int* dst = ei + N_EDGES;

    float *x0, *x1, *x2, *agg8, *cinv, *part;
    __half *yh, *aggh;
    cudaGetSymbolAddress((void**)&x0, g_x0);
    cudaGetSymbolAddress((void**)&x1, g_x1);
    cudaGetSymbolAddress((void**)&x2, g_x2);
    cudaGetSymbolAddress((void**)&yh, g_yh);
    cudaGetSymbolAddress((void**)&aggh, g_aggh);
    cudaGetSymbolAddress((void**)&agg8, g_agg8);
    cudaGetSymbolAddress((void**)&cinv, g_cinv);
    cudaGetSymbolAddress((void**)&part, g_part);

    const int NB64 = (N_NODES + 63) / 64;   // 1563

    cudaLaunchAttribute pdl_attr[1];
    pdl_attr[0].id = cudaLaunchAttributeProgrammaticStreamSerialization;
    pdl_attr[0].val.programmaticStreamSerializationAllowed = 1;

    // 1: BN partial stats
    bn_stats_kernel<<<148, 256>>>(h, part);
    // 2: BN apply + conv1 projection; zeroes agg8
    bn_conv1_kernel<<<(N_NODES + 255) / 256, 256>>>(h, part, gamma, beta, c1_pw, c1_pb,
                                                    x0, yh, agg8);
    // 3: conv1 push-scatter
    scatter8_kernel<true><<<6250, 256>>>(src, dst, ew, yh, agg8);
    // 4: fp1 with PDL (prologue overlaps scatter8<true>)
    {
        cudaLaunchConfig_t cfg = {};
        cfg.gridDim = dim3(NB64);
        cfg.blockDim = dim3(256);
        cfg.attrs = pdl_attr;
        cfg.numAttrs = 1;
        cudaLaunchKernelEx(&cfg, fp1_kernel, x0, (const float*)agg8, c1_lw, c1_lb, c1_rw,
                           c2_pw, c2_pb, c2_lw, x1, cinv, yh, aggh);
    }
    // 5: conv2 push-scatter (v4.f16x2 atomics)
    scatter64_kernel<<<4096, 256>>>(src, dst, ew, yh, aggh);
    // 6: fp2 with PDL (staging + root GEMM0 overlap scatter64)
    {
        cudaLaunchConfig_t cfg = {};
        cfg.gridDim = dim3(NB64);
        cfg.blockDim = dim3(256);
        cfg.attrs = pdl_attr;
        cfg.numAttrs = 1;
        cudaLaunchKernelEx(&cfg, fp2_kernel, (const float*)x1, (const __half*)aggh,
                           (const float*)cinv, c2_rw, c2_lb,
                           c3_pw, c3_pb, c3_lw, x2, yh, agg8);
    }
    // 7: conv3 push-scatter
    scatter8_kernel<false><<<6250, 256>>>(src, dst, ew, yh, agg8);
    // 8: fin3 with PDL (GEMM overlaps scatter8<false>)
    {
        cudaLaunchConfig_t cfg = {};
        cfg.gridDim = dim3((N_NODES + 127) / 128);
        cfg.blockDim = dim3(128);
        cfg.attrs = pdl_attr;
        cfg.numAttrs = 1;
        cudaLaunchKernelEx(&cfg, fin3_kernel, (const float*)x2, (const float*)agg8,
                           (const float*)cinv, c3_rw, c3_lb, out);
    }
}

// round 16
// speedup vs baseline: 1.0701x; 1.0174x over previous
#include <cuda_runtime.h>
#include <cuda_fp16.h>
#include <cstdint>
#include <math.h>

#define N_NODES 100000
#define N_EDGES 3200000
#define EPS_BN 1e-5f
#define EPS_NORM 1e-12f

// ---------------- device scratch (no allocation allowed) ----------------
__device__ __align__(16) float g_x0[N_NODES * 8];
__device__ __align__(16) float g_x1[N_NODES * 64];
__device__ __align__(16) float g_x2[N_NODES * 64];
__device__ __align__(16) __half g_yh[N_NODES * 64];
__device__ __align__(16) __half g_aggh[N_NODES * 64];
__device__ __align__(32) float g_agg8[N_NODES * 8];
__device__ float g_cinv[N_NODES];
__device__ __align__(16) float g_part[148 * 16];

// ---------------- vector reductions ----------------
__device__ __forceinline__ void red_add_v4(float* p, float4 v) {
    asm volatile("red.global.add.v4.f32 [%0], {%1,%2,%3,%4};"
                 :: "l"(p), "f"(v.x), "f"(v.y), "f"(v.z), "f"(v.w) : "memory");
}
__device__ __forceinline__ void red_add_v2(float* p, float a, float b) {
    asm volatile("red.global.add.v2.f32 [%0], {%1,%2};"
                 :: "l"(p), "f"(a), "f"(b) : "memory");
}
__device__ __forceinline__ void red_add_f32(float* p, float a) {
    asm volatile("red.global.add.f32 [%0], %1;"
                 :: "l"(p), "f"(a) : "memory");
}
__device__ __forceinline__ void red_add_v4_h2(__half* p, uint32_t a, uint32_t b,
                                              uint32_t c, uint32_t d) {
    asm volatile("red.global.add.noftz.v4.f16x2 [%0], {%1,%2,%3,%4};"
                 :: "l"(p), "r"(a), "r"(b), "r"(c), "r"(d) : "memory");
}

// ---------------- packed f32x2 FMA helpers ----------------
__device__ __forceinline__ unsigned long long pack2(float v) {
    unsigned long long r;
    asm("mov.b64 %0, {%1, %1};" : "=l"(r) : "f"(v));
    return r;
}
__device__ __forceinline__ unsigned long long fma2(unsigned long long a,
                                                   unsigned long long b,
                                                   unsigned long long c) {
    unsigned long long d;
    asm("fma.rn.f32x2 %0, %1, %2, %3;" : "=l"(d) : "l"(a), "l"(b), "l"(c));
    return d;
}
__device__ __forceinline__ void unpack2(unsigned long long p, float& lo, float& hi) {
    asm("mov.b64 {%0, %1}, %2;" : "=f"(lo), "=f"(hi) : "l"(p));
}

__device__ __forceinline__ int swidx(int row, int cg, int c) {
    return (row << 6) + (((cg ^ ((row >> 2) & 15)) & 15) << 2) + c;
}

// ---- K=64 GEMM via f32x2, hoisted swizzle ----
__device__ __forceinline__ void gemm64_fx2(const float* __restrict__ s_x,
                                           const float* __restrict__ s_w,
                                           int oq, int nq, float acc[4][4]) {
    unsigned long long a2[2][4];
#pragma unroll
    for (int p = 0; p < 2; p++)
#pragma unroll
        for (int k = 0; k < 4; k++) a2[p][k] = 0ull;
#pragma unroll
    for (int i4 = 0; i4 < 16; i4++) {
        const float* xb = &s_x[(i4 << 8) + (((nq ^ i4) & 15) << 2)];
        const float* wb = &s_w[(i4 << 8) + (oq << 2)];
#pragma unroll
        for (int j = 0; j < 4; j++) {
            ulonglong2 xp = *reinterpret_cast<const ulonglong2*>(xb + (j << 6));
            float4 wv = *reinterpret_cast<const float4*>(wb + (j << 6));
            unsigned long long w0 = pack2(wv.x), w1 = pack2(wv.y);
            unsigned long long w2 = pack2(wv.z), w3 = pack2(wv.w);
            a2[0][0] = fma2(xp.x, w0, a2[0][0]);
            a2[0][1] = fma2(xp.x, w1, a2[0][1]);
            a2[0][2] = fma2(xp.x, w2, a2[0][2]);
            a2[0][3] = fma2(xp.x, w3, a2[0][3]);
            a2[1][0] = fma2(xp.y, w0, a2[1][0]);
            a2[1][1] = fma2(xp.y, w1, a2[1][1]);
            a2[1][2] = fma2(xp.y, w2, a2[1][2]);
            a2[1][3] = fma2(xp.y, w3, a2[1][3]);
        }
    }
#pragma unroll
    for (int k = 0; k < 4; k++) {
        unpack2(a2[0][k], acc[0][k], acc[1][k]);
        unpack2(a2[1][k], acc[2][k], acc[3][k]);
    }
}

// ------- BatchNorm statistics -------
__global__ __launch_bounds__(256) void bn_stats_kernel(const float* __restrict__ h,
                                                       float* __restrict__ part) {
    float s[5] = {0, 0, 0, 0, 0}, q[5] = {0, 0, 0, 0, 0};
    int stride = gridDim.x * blockDim.x;
    for (int n = blockIdx.x * blockDim.x + threadIdx.x; n < N_NODES; n += stride) {
#pragma unroll
        for (int i = 0; i < 5; i++) {
            float v = h[n * 5 + i];
            s[i] += v;
            q[i] += v * v;
        }
    }
#pragma unroll
    for (int k = 16; k > 0; k >>= 1) {
#pragma unroll
        for (int i = 0; i < 5; i++) {
            s[i] += __shfl_down_sync(0xffffffffu, s[i], k);
            q[i] += __shfl_down_sync(0xffffffffu, q[i], k);
        }
    }
    __shared__ float sh[10];
    if (threadIdx.x < 10) sh[threadIdx.x] = 0.f;
    __syncthreads();
    if ((threadIdx.x & 31) == 0) {
#pragma unroll
        for (int i = 0; i < 5; i++) {
            atomicAdd(&sh[i], s[i]);
            atomicAdd(&sh[5 + i], q[i]);
        }
    }
    __syncthreads();
    if (threadIdx.x < 10) part[blockIdx.x * 16 + threadIdx.x] = sh[threadIdx.x];
}

// ------- BN apply + conv1 projection -> fp16 y8 ; zero agg8 -------
__global__ __launch_bounds__(256) void bn_conv1_kernel(const float* __restrict__ h,
                                                       const float* __restrict__ part,
                                                       const float* __restrict__ gamma,
                                                       const float* __restrict__ beta,
                                                       const float* __restrict__ pw,
                                                       const float* __restrict__ pb,
                                                       float* __restrict__ x0p,
                                                       __half* __restrict__ y8,
                                                       float* __restrict__ agg8) {
    __shared__ float s_warp[8][10];
    __shared__ float s_stats[10];
    int t = threadIdx.x;
    int lane = t & 31, wid = t >> 5;
    {
        float v[10];
#pragma unroll
        for (int i = 0; i < 10; i++) v[i] = 0.f;
        if (t < 148) {
#pragma unroll
            for (int i = 0; i < 10; i++) v[i] = part[t * 16 + i];
        }
#pragma unroll
        for (int k = 16; k > 0; k >>= 1) {
#pragma unroll
            for (int i = 0; i < 10; i++) v[i] += __shfl_down_sync(0xffffffffu, v[i], k);
        }
        if (lane == 0) {
#pragma unroll
            for (int i = 0; i < 10; i++) s_warp[wid][i] = v[i];
        }
    }
    __syncthreads();
    if (t < 10) {
        float acc = 0.f;
#pragma unroll
        for (int w = 0; w < 8; w++) acc += s_warp[w][t];
        s_stats[t] = acc;
    }
    __syncthreads();

    int n = blockIdx.x * blockDim.x + t;
    if (n >= N_NODES) return;
    const float inv_n = 1.f / (float)N_NODES;
    float xr[5];
#pragma unroll
    for (int i = 0; i < 5; i++) {
        float mu = s_stats[i] * inv_n;
        float var = s_stats[5 + i] * inv_n - mu * mu;
        float sc = rsqrtf(var + EPS_BN) * gamma[i];
        xr[i] = (h[n * 5 + i] - mu) * sc + beta[i];
    }
    float4* x0v = reinterpret_cast<float4*>(x0p + (size_t)n * 8);
    x0v[0] = make_float4(xr[0], xr[1], xr[2], xr[3]);
    x0v[1] = make_float4(xr[4], 0.f, 0.f, 0.f);
    float xp[5];
#pragma unroll
    for (int k = 0; k < 5; k++) {
        float v = pb[k];
#pragma unroll
        for (int i = 0; i < 5; i++) v += xr[i] * pw[i * 5 + k];
        xp[k] = fmaxf(v, 0.f);
    }
    __half2 h0 = __floats2half2_rn(xp[0], xp[1]);
    __half2 h1 = __floats2half2_rn(xp[2], xp[3]);
    __half2 h2 = __floats2half2_rn(xp[4], 0.f);
    uint4 pack;
    pack.x = *reinterpret_cast<uint32_t*>(&h0);
    pack.y = *reinterpret_cast<uint32_t*>(&h1);
    pack.z = *reinterpret_cast<uint32_t*>(&h2);
    pack.w = 0u;
    *reinterpret_cast<uint4*>(y8 + (size_t)n * 8) = pack;
    float4* av = reinterpret_cast<float4*>(agg8 + (size_t)n * 8);
    float4 z = make_float4(0.f, 0.f, 0.f, 0.f);
    av[0] = z;
    av[1] = z;
}

// -------- width-8 push scatter (PDL: index prefetch before sync) --------
template <bool ADD_CNT>
__global__ void scatter8_kernel(const int* __restrict__ src,
                                const int* __restrict__ dst,
                                const float* __restrict__ ew,
                                const __half* __restrict__ y8,
                                float* __restrict__ agg8) {
    int stride = gridDim.x * blockDim.x;
    int e = blockIdx.x * blockDim.x + threadIdx.x;
    int s = 0, d = 0;
    float w = 0.f;
    bool have = e < N_EDGES;
    if (have) {
        s = __ldg(&src[e]);
        d = __ldg(&dst[e]);
        w = __ldg(&ew[e]);
    }
#if __CUDA_ARCH__ >= 900
    cudaGridDependencySynchronize();
#endif
    while (have) {
        uint4 raw = *reinterpret_cast<const uint4*>(y8 + (size_t)s * 8);
        float2 f0 = __half22float2(*reinterpret_cast<__half2*>(&raw.x));
        float2 f1 = __half22float2(*reinterpret_cast<__half2*>(&raw.y));
        float2 f2 = __half22float2(*reinterpret_cast<__half2*>(&raw.z));
        float* base = agg8 + (size_t)d * 8;
        float cw = f2.x * w;
        red_add_v4(base, make_float4(f0.x * w, f0.y * w, f1.x * w, f1.y * w));
        if (ADD_CNT)
            red_add_v2(base + 4, cw, 1.0f);
        else
            red_add_f32(base + 4, cw);
        e += stride;
        have = e < N_EDGES;
        if (have) {
            s = __ldg(&src[e]);
            d = __ldg(&dst[e]);
            w = __ldg(&ew[e]);
        }
    }
}

// -------- width-64 push scatter: 8 lanes/edge, v4.f16x2, PDL prefetch --------
__global__ void scatter64_kernel(const int* __restrict__ src,
                                 const int* __restrict__ dst,
                                 const float* __restrict__ ew,
                                 const __half* __restrict__ y,
                                 __half* __restrict__ agg) {
    int lane = threadIdx.x & 31;
    int warp = (blockIdx.x * blockDim.x + threadIdx.x) >> 5;
    int nwarps = (gridDim.x * blockDim.x) >> 5;
    int quarter = lane >> 3;
    int fo = (lane & 7) << 3;
    const int ngroups = N_EDGES / 4;
    int p = warp;
    int s = 0, d = 0;
    float w = 0.f;
    bool have = p < ngroups;
    if (have) {
        int e = 4 * p + quarter;
        s = __ldg(&src[e]);
        d = __ldg(&dst[e]);
        w = __ldg(&ew[e]);
    }
#if __CUDA_ARCH__ >= 900
    cudaGridDependencySynchronize();
#endif
    while (have) {
        uint4 raw = *reinterpret_cast<const uint4*>(y + (size_t)s * 64 + fo);
        float2 f0 = __half22float2(*reinterpret_cast<__half2*>(&raw.x));
        float2 f1 = __half22float2(*reinterpret_cast<__half2*>(&raw.y));
        float2 f2 = __half22float2(*reinterpret_cast<__half2*>(&raw.z));
        float2 f3 = __half22float2(*reinterpret_cast<__half2*>(&raw.w));
        __half2 h0 = __floats2half2_rn(f0.x * w, f0.y * w);
        __half2 h1 = __floats2half2_rn(f1.x * w, f1.y * w);
        __half2 h2 = __floats2half2_rn(f2.x * w, f2.y * w);
        __half2 h3 = __floats2half2_rn(f3.x * w, f3.y * w);
        red_add_v4_h2(agg + (size_t)d * 64 + fo,
                      *reinterpret_cast<uint32_t*>(&h0),
                      *reinterpret_cast<uint32_t*>(&h1),
                      *reinterpret_cast<uint32_t*>(&h2),
                      *reinterpret_cast<uint32_t*>(&h3));
        p += nwarps;
        have = p < ngroups;
        if (have) {
            int e = 4 * p + quarter;
            s = __ldg(&src[e]);
            d = __ldg(&dst[e]);
            w = __ldg(&ew[e]);
        }
    }
}

// ==================== fp1: conv1 finalize + conv2 projection (PDL) ====================
__global__ __launch_bounds__(256, 5) void fp1_kernel(const float* __restrict__ x0p,
                                                     const float* __restrict__ agg8,
                                                     const float* __restrict__ lw1,
                                                     const float* __restrict__ lb1,
                                                     const float* __restrict__ rw1,
                                                     const float* __restrict__ pw2,
                                                     const float* __restrict__ pb2,
                                                     const float* __restrict__ lw2,
                                                     float* __restrict__ x1,
                                                     float* __restrict__ cinv_out,
                                                     __half* __restrict__ y,
                                                     __half* __restrict__ aggh_zero) {
    __shared__ float s_w[64 * 64];
    __shared__ float s_x[64 * 64];
    __shared__ float s_b[64];
    __shared__ float s_ci[64];
    const int t = threadIdx.x;
    const int n0 = blockIdx.x * 64;
    const int oq = t & 15, nq = t >> 4;

    {
        float4 z = make_float4(0.f, 0.f, 0.f, 0.f);
        float4* zb = reinterpret_cast<float4*>(aggh_zero);
        int base = blockIdx.x * 512;
        for (int i = t; i < 512; i += 256) {
            int gi = base + i;
            if (gi < N_NODES * 8) zb[gi] = z;
        }
    }
    for (int idx = t; idx < 640; idx += 256)
        s_w[idx] = (idx < 320) ? lw1[idx] : rw1[idx - 320];
    if (t < 64) s_b[t] = lb1[t];

#if __CUDA_ARCH__ >= 900
    cudaGridDependencySynchronize();
#endif

    if (t < 64) {
        int nn = min(n0 + t, N_NODES - 1);
        float c = agg8[(size_t)nn * 8 + 5];
        float ci = 1.f / fmaxf(c, 1.f);
        s_ci[t] = ci;
        if (n0 + t < N_NODES) cinv_out[n0 + t] = ci;
    }
    __syncthreads();
    for (int idx = t; idx < 640; idx += 256) {
        int i = idx >> 6, nd = idx & 63;
        int nn = min(n0 + nd, N_NODES - 1);
        s_x[i * 72 + nd] = (i < 5) ? agg8[(size_t)nn * 8 + i] * s_ci[nd]
                                   : x0p[(size_t)nn * 8 + (i - 5)];
    }
    __syncthreads();

    // ---- GEMM0: K=10 ----
    float acc[4][4];
#pragma unroll
    for (int a = 0; a < 4; a++)
#pragma unroll
        for (int b = 0; b < 4; b++) acc[a][b] = 0.f;
#pragma unroll
    for (int i = 0; i < 10; i++) {
        float4 xv = *reinterpret_cast<const float4*>(&s_x[i * 72 + (nq << 2)]);
        float4 wv = *reinterpret_cast<const float4*>(&s_w[(i << 6) + (oq << 2)]);
        acc[0][0] += xv.x * wv.x; acc[0][1] += xv.x * wv.y; acc[0][2] += xv.x * wv.z; acc[0][3] += xv.x * wv.w;
        acc[1][0] += xv.y * wv.x; acc[1][1] += xv.y * wv.y; acc[1][2] += xv.y * wv.z; acc[1][3] += xv.y * wv.w;
        acc[2][0] += xv.z * wv.x; acc[2][1] += xv.z * wv.y; acc[2][2] += xv.z * wv.z; acc[2][3] += xv.z * wv.w;
        acc[3][0] += xv.w * wv.x; acc[3][1] += xv.w * wv.y; acc[3][2] += xv.w * wv.z; acc[3][3] += xv.w * wv.w;
    }
    float lb0 = s_b[(oq << 2) + 0], lb1v = s_b[(oq << 2) + 1];
    float lb2 = s_b[(oq << 2) + 2], lb3 = s_b[(oq << 2) + 3];
#pragma unroll
    for (int dn = 0; dn < 4; dn++) {
        float v0 = acc[dn][0] + lb0;
        float v1 = acc[dn][1] + lb1v;
        float v2 = acc[dn][2] + lb2;
        float v3 = acc[dn][3] + lb3;
        float ss = v0 * v0 + v1 * v1 + v2 * v2 + v3 * v3;
        ss += __shfl_down_sync(0xffffffffu, ss, 8, 16);
        ss += __shfl_down_sync(0xffffffffu, ss, 4, 16);
        ss += __shfl_down_sync(0xffffffffu, ss, 2, 16);
        ss += __shfl_down_sync(0xffffffffu, ss, 1, 16);
        ss = __shfl_sync(0xffffffffu, ss, 0, 16);
        float sc = 1.f / fmaxf(sqrtf(ss), EPS_NORM);
        acc[dn][0] = fmaxf(v0 * sc, 0.f);
        acc[dn][1] = fmaxf(v1 * sc, 0.f);
        acc[dn][2] = fmaxf(v2 * sc, 0.f);
        acc[dn][3] = fmaxf(v3 * sc, 0.f);
    }
    __syncthreads();

#pragma unroll
    for (int dn = 0; dn < 4; dn++) {
        int n = n0 + (nq << 2) + dn;
        if (n < N_NODES) {
            *reinterpret_cast<float4*>(&x1[(size_t)n * 64 + (oq << 2)]) =
                make_float4(acc[dn][0], acc[dn][1], acc[dn][2], acc[dn][3]);
        }
#pragma unroll
        for (int dk = 0; dk < 4; dk++)
            s_x[swidx((oq << 2) + dk, nq, dn)] = acc[dn][dk];
    }
    for (int i4 = t; i4 < 1024; i4 += 256)
        reinterpret_cast<float4*>(s_w)[i4] = reinterpret_cast<const float4*>(pw2)[i4];
    if (t < 64) s_b[t] = pb2[t];
    __syncthreads();

    // ---- GEMM1 ----
    gemm64_fx2(s_x, s_w, oq, nq, acc);
    __syncthreads();
#pragma unroll
    for (int dk = 0; dk < 4; dk++) {
        float b = s_b[(oq << 2) + dk];
#pragma unroll
        for (int dn = 0; dn < 4; dn++)
            s_x[swidx((oq << 2) + dk, nq, dn)] = fmaxf(acc[dn][dk] + b, 0.f);
    }
    for (int i4 = t; i4 < 1024; i4 += 256)
        reinterpret_cast<float4*>(s_w)[i4] = reinterpret_cast<const float4*>(lw2)[i4];
    __syncthreads();

    // ---- GEMM2 -> y fp16 ----
    gemm64_fx2(s_x, s_w, oq, nq, acc);
#pragma unroll
    for (int dn = 0; dn < 4; dn++) {
        int n = n0 + (nq << 2) + dn;
        if (n < N_NODES) {
            __half2 h0 = __floats2half2_rn(acc[dn][0], acc[dn][1]);
            __half2 h1 = __floats2half2_rn(acc[dn][2], acc[dn][3]);
            uint2 pack;
            pack.x = *reinterpret_cast<uint32_t*>(&h0);
            pack.y = *reinterpret_cast<uint32_t*>(&h1);
            *reinterpret_cast<uint2*>(y + (size_t)n * 64 + (oq << 2)) = pack;
        }
    }
}

// ==================== fp2: conv2 finalize + conv3 projection (PDL) ====================
__global__ __launch_bounds__(256, 5) void fp2_kernel(const float* __restrict__ x1,
                                                     const __half* __restrict__ agg,
                                                     const float* __restrict__ cinv,
                                                     const float* __restrict__ rw2,
                                                     const float* __restrict__ lb2,
                                                     const float* __restrict__ pw3,
                                                     const float* __restrict__ pb3,
                                                     const float* __restrict__ lw3,
                                                     float* __restrict__ x2,
                                                     __half* __restrict__ y8,
                                                     float* __restrict__ agg8z) {
    __shared__ float s_w[64 * 64];
    __shared__ float s_x[64 * 64];
    __shared__ float s_b[64];
    const int t = threadIdx.x;
    const int n0 = blockIdx.x * 64;
    const int oq = t & 15, nq = t >> 4;

    if (t < 128) {
        int gi = blockIdx.x * 128 + t;
        if (gi < N_NODES * 2) {
            float4 z = make_float4(0.f, 0.f, 0.f, 0.f);
            reinterpret_cast<float4*>(agg8z)[gi] = z;
        }
    }
    for (int i4 = t; i4 < 1024; i4 += 256)
        reinterpret_cast<float4*>(s_w)[i4] = reinterpret_cast<const float4*>(rw2)[i4];
    if (t < 64) s_b[t] = lb2[t];
    for (int idx = t; idx < 64 * 64; idx += 256) {
        int n = idx >> 6, i = idx & 63;
        int nn = min(n0 + n, N_NODES - 1);
        s_x[swidx(i, n >> 2, n & 3)] = x1[(size_t)nn * 64 + i];
    }
    __syncthreads();

    // ---- GEMM0: root term (scatter-independent) ----
    float acc[4][4];
    gemm64_fx2(s_x, s_w, oq, nq, acc);

#if __CUDA_ARCH__ >= 900
    cudaGridDependencySynchronize();
#endif

    float lb0 = s_b[(oq << 2) + 0], lb1v = s_b[(oq << 2) + 1];
    float lb2v = s_b[(oq << 2) + 2], lb3 = s_b[(oq << 2) + 3];
#pragma unroll
    for (int dn = 0; dn < 4; dn++) {
        int n = n0 + (nq << 2) + dn;
        int nn = min(n, N_NODES - 1);
        float ci = cinv[nn];
        uint2 raw = *reinterpret_cast<const uint2*>(agg + (size_t)nn * 64 + (oq << 2));
        float2 g0 = __half22float2(*reinterpret_cast<__half2*>(&raw.x));
        float2 g1 = __half22float2(*reinterpret_cast<__half2*>(&raw.y));
        float v0 = acc[dn][0] + lb0 + g0.x * ci;
        float v1 = acc[dn][1] + lb1v + g0.y * ci;
        float v2 = acc[dn][2] + lb2v + g1.x * ci;
        float v3 = acc[dn][3] + lb3 + g1.y * ci;
        float ss = v0 * v0 + v1 * v1 + v2 * v2 + v3 * v3;
        ss += __shfl_down_sync(0xffffffffu, ss, 8, 16);
        ss += __shfl_down_sync(0xffffffffu, ss, 4, 16);
        ss += __shfl_down_sync(0xffffffffu, ss, 2, 16);
        ss += __shfl_down_sync(0xffffffffu, ss, 1, 16);
        ss = __shfl_sync(0xffffffffu, ss, 0, 16);
        float sc = 1.f / fmaxf(sqrtf(ss), EPS_NORM);
        acc[dn][0] = fmaxf(v0 * sc, 0.f);
        acc[dn][1] = fmaxf(v1 * sc, 0.f);
        acc[dn][2] = fmaxf(v2 * sc, 0.f);
        acc[dn][3] = fmaxf(v3 * sc, 0.f);
    }
    __syncthreads();

#pragma unroll
    for (int dn = 0; dn < 4; dn++) {
        int n = n0 + (nq << 2) + dn;
        if (n < N_NODES) {
            *reinterpret_cast<float4*>(&x2[(size_t)n * 64 + (oq << 2)]) =
                make_float4(acc[dn][0], acc[dn][1], acc[dn][2], acc[dn][3]);
        }
#pragma unroll
        for (int dk = 0; dk < 4; dk++)
            s_x[swidx((oq << 2) + dk, nq, dn)] = acc[dn][dk];
    }
    for (int i4 = t; i4 < 1024; i4 += 256)
        reinterpret_cast<float4*>(s_w)[i4] = reinterpret_cast<const float4*>(pw3)[i4];
    if (t < 64) s_b[t] = pb3[t];
    __syncthreads();

    // ---- GEMM1 ----
    gemm64_fx2(s_x, s_w, oq, nq, acc);
    __syncthreads();
#pragma unroll
    for (int dk = 0; dk < 4; dk++) {
        float b = s_b[(oq << 2) + dk];
#pragma unroll
        for (int dn = 0; dn < 4; dn++)
            s_x[swidx((oq << 2) + dk, nq, dn)] = fmaxf(acc[dn][dk] + b, 0.f);
    }
    for (int idx = t; idx < 64 * 8; idx += 256) s_w[idx] = 0.f;
    __syncthreads();
    for (int idx = t; idx < 64 * 5; idx += 256) s_w[(idx / 5) * 8 + (idx % 5)] = lw3[idx];
    __syncthreads();

    // ---- GEMM2: y8 = xp @ lw3 ----
    if (oq < 2) {
        float a2[4][4];
#pragma unroll
        for (int a = 0; a < 4; a++)
#pragma unroll
            for (int b = 0; b < 4; b++) a2[a][b] = 0.f;
#pragma unroll
        for (int i4 = 0; i4 < 16; i4++) {
            const float* xb = &s_x[(i4 << 8) + (((nq ^ i4) & 15) << 2)];
            const float* wb = &s_w[(i4 << 5) + (oq << 2)];
#pragma unroll
            for (int j = 0; j < 4; j++) {
                float4 xv = *reinterpret_cast<const float4*>(xb + (j << 6));
                float4 wv = *reinterpret_cast<const float4*>(wb + (j << 3));
                a2[0][0] += xv.x * wv.x; a2[0][1] += xv.x * wv.y; a2[0][2] += xv.x * wv.z; a2[0][3] += xv.x * wv.w;
                a2[1][0] += xv.y * wv.x; a2[1][1] += xv.y * wv.y; a2[1][2] += xv.y * wv.z; a2[1][3] += xv.y * wv.w;
                a2[2][0] += xv.z * wv.x; a2[2][1] += xv.z * wv.y; a2[2][2] += xv.z * wv.z; a2[2][3] += xv.z * wv.w;
                a2[3][0] += xv.w * wv.x; a2[3][1] += xv.w * wv.y; a2[3][2] += xv.w * wv.z; a2[3][3] += xv.w * wv.w;
            }
        }
#pragma unroll
        for (int dn = 0; dn < 4; dn++) {
            int n = n0 + (nq << 2) + dn;
            if (n < N_NODES) {
                __half2 h0 = __floats2half2_rn(a2[dn][0], a2[dn][1]);
                __half2 h1 = __floats2half2_rn(a2[dn][2], a2[dn][3]);
                uint2 pack;
                pack.x = *reinterpret_cast<uint32_t*>(&h0);
                pack.y = *reinterpret_cast<uint32_t*>(&h1);
                *reinterpret_cast<uint2*>(y8 + (size_t)n * 8 + (oq << 2)) = pack;
            }
        }
    }
}

// ------- conv3 finalize (PDL): GEMM first, agg terms after sync -------
__global__ __launch_bounds__(128) void fin3_kernel(const float* __restrict__ x2,
                                                   const float* __restrict__ agg8,
                                                   const float* __restrict__ cinv,
                                                   const float* __restrict__ rw,
                                                   const float* __restrict__ lb,
                                                   float* __restrict__ out) {
    __shared__ float s_rw[64 * 8];
    __shared__ float s_lb[8];
    int t = threadIdx.x;
    for (int idx = t; idx < 320; idx += 128) s_rw[(idx / 5) * 8 + (idx % 5)] = rw[idx];
    if (t < 5) s_lb[t] = lb[t];
    __syncthreads();
    int n = blockIdx.x * 128 + t;
    if (n >= N_NODES) n = N_NODES - 1;

    float4 vf = make_float4(0.f, 0.f, 0.f, 0.f);
    float v4 = 0.f;
    const float4* xr = reinterpret_cast<const float4*>(x2 + (size_t)n * 64);
#pragma unroll
    for (int iq = 0; iq < 16; iq++) {
        float4 xv = xr[iq];
        float xs[4] = {xv.x, xv.y, xv.z, xv.w};
#pragma unroll
        for (int c = 0; c < 4; c++) {
            int i = iq * 4 + c;
            float4 w = *reinterpret_cast<const float4*>(&s_rw[i * 8]);
            float w4 = s_rw[i * 8 + 4];
            vf.x += xs[c] * w.x;
            vf.y += xs[c] * w.y;
            vf.z += xs[c] * w.z;
            vf.w += xs[c] * w.w;
            v4 += xs[c] * w4;
        }
    }

#if __CUDA_ARCH__ >= 900
    cudaGridDependencySynchronize();
#endif

    float ci = cinv[n];
    const float4* av = reinterpret_cast<const float4*>(agg8 + (size_t)n * 8);
    float4 a0 = av[0], a1 = av[1];
    vf.x += s_lb[0] + a0.x * ci;
    vf.y += s_lb[1] + a0.y * ci;
    vf.z += s_lb[2] + a0.z * ci;
    vf.w += s_lb[3] + a0.w * ci;
    v4 += s_lb[4] + a1.x * ci;

    float ss = vf.x * vf.x + vf.y * vf.y + vf.z * vf.z + vf.w * vf.w + v4 * v4;
    float sc = 1.f / fmaxf(sqrtf(ss), EPS_NORM);
    int nout = blockIdx.x * 128 + t;
    if (nout < N_NODES) {
        float* o = out + (size_t)nout * 5;
        o[0] = vf.x * sc;
        o[1] = vf.y * sc;
        o[2] = vf.z * sc;
        o[3] = vf.w * sc;
        o[4] = v4 * sc;
    }
}

// ---------------- host launcher ----------------
extern "C" void kernel_launch(void* const* d_in, const int* in_sizes, int n_in,
                              void* d_out, int out_size) {
    const float* h = (const float*)d_in[0];
    const int* ei = (const int*)d_in[1];
    const float* ew = (const float*)d_in[2];
    const float* gamma = (const float*)d_in[3];
    const float* beta = (const float*)d_in[4];
    const float* c1_pw = (const float*)d_in[5];
    const float* c1_pb = (const float*)d_in[6];
    const float* c1_lw = (const float*)d_in[7];
    const float* c1_lb = (const float*)d_in[8];
    const float* c1_rw = (const float*)d_in[9];
    const float* c2_pw = (const float*)d_in[10];
    const float* c2_pb = (const float*)d_in[11];
    const float* c2_lw = (const float*)d_in[12];
    const float* c2_lb = (const float*)d_in[13];
    const float* c2_rw = (const float*)d_in[14];
    const float* c3_pw = (const float*)d_in[15];
    const float* c3_pb = (const float*)d_in[16];
    const float* c3_lw = (const float*)d_in[17];
    const float* c3_lb = (const float*)d_in[18];
    const float* c3_rw = (const float*)d_in[19];
    float* out = (float*)d_out;

    const int* src = ei;
    const int* dst = ei + N_EDGES;

    float *x0, *x1, *x2, *agg8, *cinv, *part;
    __half *yh, *aggh;
    cudaGetSymbolAddress((void**)&x0, g_x0);
    cudaGetSymbolAddress((void**)&x1, g_x1);
    cudaGetSymbolAddress((void**)&x2, g_x2);
    cudaGetSymbolAddress((void**)&yh, g_yh);
    cudaGetSymbolAddress((void**)&aggh, g_aggh);
    cudaGetSymbolAddress((void**)&agg8, g_agg8);
    cudaGetSymbolAddress((void**)&cinv, g_cinv);
    cudaGetSymbolAddress((void**)&part, g_part);

    const int NB64 = (N_NODES + 63) / 64;

    cudaLaunchAttribute pdl_attr[1];
    pdl_attr[0].id = cudaLaunchAttributeProgrammaticStreamSerialization;
    pdl_attr[0].val.programmaticStreamSerializationAllowed = 1;

    // 1: BN partial stats
    bn_stats_kernel<<<148, 256>>>(h, part);
    // 2: BN apply + conv1 projection; zeroes agg8
    bn_conv1_kernel<<<(N_NODES + 255) / 256, 256>>>(h, part, gamma, beta, c1_pw, c1_pb,
                                                    x0, yh, agg8);
    // 3: conv1 push-scatter (PDL: prefetch indices during bn_conv1 tail)
    {
        cudaLaunchConfig_t cfg = {};
        cfg.gridDim = dim3(6250);
        cfg.blockDim = dim3(256);
        cfg.attrs = pdl_attr;
        cfg.numAttrs = 1;
        cudaLaunchKernelEx(&cfg, scatter8_kernel<true>, src, dst, ew,
                           (const __half*)yh, agg8);
    }
    // 4: fp1 with PDL (prologue overlaps scatter8<true>)
    {
        cudaLaunchConfig_t cfg = {};
        cfg.gridDim = dim3(NB64);
        cfg.blockDim = dim3(256);
        cfg.attrs = pdl_attr;
        cfg.numAttrs = 1;
        cudaLaunchKernelEx(&cfg, fp1_kernel, x0, (const float*)agg8, c1_lw, c1_lb, c1_rw,
                           c2_pw, c2_pb, c2_lw, x1, cinv, yh, aggh);
    }
    // 5: conv2 push-scatter (PDL: prefetch indices during fp1 tail)
    {
        cudaLaunchConfig_t cfg = {};
        cfg.gridDim = dim3(4096);
        cfg.blockDim = dim3(256);
        cfg.attrs = pdl_attr;
        cfg.numAttrs = 1;
        cudaLaunchKernelEx(&cfg, scatter64_kernel, src, dst, ew,
                           (const __half*)yh, aggh);
    }
    // 6: fp2 with PDL (staging + root GEMM0 overlap scatter64)
    {
        cudaLaunchConfig_t cfg = {};
        cfg.gridDim = dim3(NB64);
        cfg.blockDim = dim3(256);
        cfg.attrs = pdl_attr;
        cfg.numAttrs = 1;
        cudaLaunchKernelEx(&cfg, fp2_kernel, (const float*)x1, (const __half*)aggh,
                           (const float*)cinv, c2_rw, c2_lb,
                           c3_pw, c3_pb, c3_lw, x2, yh, agg8);
    }
    // 7: conv3 push-scatter (PDL)
    {
        cudaLaunchConfig_t cfg = {};
        cfg.gridDim = dim3(6250);
        cfg.blockDim = dim3(256);
        cfg.attrs = pdl_attr;
        cfg.numAttrs = 1;
        cudaLaunchKernelEx(&cfg, scatter8_kernel<false>, src, dst, ew,
                           (const __half*)yh, agg8);
    }
    // 8: fin3 with PDL (GEMM overlaps scatter8<false>)
    {
        cudaLaunchConfig_t cfg = {};
        cfg.gridDim = dim3((N_NODES + 127) / 128);
        cfg.blockDim = dim3(128);
        cfg.attrs = pdl_attr;
        cfg.numAttrs = 1;
        cudaLaunchKernelEx(&cfg, fin3_kernel, (const float*)x2, (const float*)agg8,
                           (const float*)cinv, c3_rw, c3_lb, out);
    }
}